// round 2
// baseline (speedup 1.0000x reference)
#include <cuda_runtime.h>
#include <cuda_bf16.h>
#include <cstdint>

// Problem constants
#define BATCH 2
#define SEQ   2048
#define CDIM  1024
#define NHEAD 16
#define HDIM  64
#define MROWS (BATCH*SEQ)      // 4096
#define BSIZE 102

// Scratch (device globals: allocation-free)
__device__ float g_q[BATCH*NHEAD*SEQ*HDIM];   // [B,H,T,D]
__device__ float g_k[BATCH*NHEAD*SEQ*HDIM];
__device__ float g_v[BATCH*NHEAD*SEQ*HDIM];
__device__ float g_att[MROWS*CDIM];           // [B,T,C]

// ---------------------------------------------------------------------------
// Generic tiled GEMM: C[M,N] = A[M,K] @ W[K,N] + bias
// M=4096, N=K=1024. BM=BN=64, BK=16, 256 threads, 4x4 per thread.
// mode 0: scatter output into [B,H,T,D] layout (for q/k/v)
// mode 1: plain row-major [M,N]
// ---------------------------------------------------------------------------
__global__ __launch_bounds__(256)
void gemm64(const float* __restrict__ A, const float* __restrict__ W,
            const float* __restrict__ bias, float* __restrict__ C, int mode)
{
    const int K = CDIM, N = CDIM;
    __shared__ float As[16][64];
    __shared__ float Bs[16][64];

    const int tid = threadIdx.x;
    const int tx = tid & 15;          // 0..15 -> col group
    const int ty = tid >> 4;          // 0..15 -> row group
    const int rowBase = blockIdx.y * 64;
    const int colBase = blockIdx.x * 64;

    // A-tile load mapping: 64 rows x 16 cols, float4 per thread
    const int laRow = tid >> 2;          // 0..63
    const int laCol = (tid & 3) * 4;     // 0,4,8,12
    // B-tile load mapping: 16 rows x 64 cols, float4 per thread
    const int lbRow = tid >> 4;          // 0..15
    const int lbCol = (tid & 15) * 4;    // 0..60

    float acc[4][4] = {};

    for (int k0 = 0; k0 < K; k0 += 16) {
        float4 a4 = *reinterpret_cast<const float4*>(
            &A[(size_t)(rowBase + laRow) * K + k0 + laCol]);
        As[laCol + 0][laRow] = a4.x;
        As[laCol + 1][laRow] = a4.y;
        As[laCol + 2][laRow] = a4.z;
        As[laCol + 3][laRow] = a4.w;

        float4 b4 = *reinterpret_cast<const float4*>(
            &W[(size_t)(k0 + lbRow) * N + colBase + lbCol]);
        *reinterpret_cast<float4*>(&Bs[lbRow][lbCol]) = b4;

        __syncthreads();

        #pragma unroll
        for (int kk = 0; kk < 16; ++kk) {
            float a[4], b[4];
            #pragma unroll
            for (int i = 0; i < 4; ++i) a[i] = As[kk][ty * 4 + i];
            #pragma unroll
            for (int j = 0; j < 4; ++j) b[j] = Bs[kk][tx * 4 + j];
            #pragma unroll
            for (int i = 0; i < 4; ++i)
                #pragma unroll
                for (int j = 0; j < 4; ++j)
                    acc[i][j] = fmaf(a[i], b[j], acc[i][j]);
        }
        __syncthreads();
    }

    #pragma unroll
    for (int i = 0; i < 4; ++i) {
        const int r = rowBase + ty * 4 + i;
        #pragma unroll
        for (int j = 0; j < 4; ++j) {
            const int c = colBase + tx * 4 + j;
            const float val = acc[i][j] + bias[c];
            if (mode == 0) {
                // scatter to [B,H,T,D]
                const int b = r >> 11;          // /SEQ
                const int t = r & (SEQ - 1);
                const int h = c >> 6;           // /HDIM
                const int d = c & (HDIM - 1);
                C[(((size_t)b * NHEAD + h) * SEQ + t) * HDIM + d] = val;
            } else {
                C[(size_t)r * N + c] = val;
            }
        }
    }
}

// ---------------------------------------------------------------------------
// Causal flash attention. grid = (T/64, B*H), block = 64 threads.
// Each thread owns one query row: q[64] and O[64] in registers.
// K/V tiles staged in smem (broadcast reads). Writes [B,T,C].
// ---------------------------------------------------------------------------
__global__ __launch_bounds__(64)
void attn_kernel(float* __restrict__ out)
{
    const int qt  = blockIdx.x;          // query tile, 0..31
    const int bh  = blockIdx.y;          // 0..31
    const int b   = bh >> 4;
    const int h   = bh & 15;
    const int row = threadIdx.x;         // 0..63
    const int qi  = qt * 64 + row;       // global query index

    __shared__ float Ks[64][64];
    __shared__ float Vs[64][64];
    __shared__ float S[64][64];          // S[j][row]: conflict-free per-thread column

    const float* qbase = g_q + ((size_t)bh * SEQ + qi) * HDIM;
    float qr[HDIM];
    #pragma unroll
    for (int d = 0; d < HDIM; ++d) qr[d] = qbase[d];

    float O[HDIM];
    #pragma unroll
    for (int d = 0; d < HDIM; ++d) O[d] = 0.f;
    float m = -1e30f, l = 0.f;

    const float scale = 0.125f;          // 1/sqrt(64)
    const float* ktile0 = g_k + (size_t)bh * SEQ * HDIM;
    const float* vtile0 = g_v + (size_t)bh * SEQ * HDIM;

    for (int jt = 0; jt <= qt; ++jt) {
        const float* kt = ktile0 + (size_t)jt * 64 * HDIM;
        const float* vt = vtile0 + (size_t)jt * 64 * HDIM;
        __syncthreads();
        // coalesced tile load: thread `row` loads element (i, row) of each tile
        for (int i = 0; i < 64; ++i) {
            Ks[i][row] = kt[i * HDIM + row];
            Vs[i][row] = vt[i * HDIM + row];
        }
        __syncthreads();

        const bool diag = (jt == qt);
        float mt = -1e30f;
        for (int j = 0; j < 64; ++j) {
            float acc = 0.f;
            #pragma unroll
            for (int d = 0; d < HDIM; ++d) acc = fmaf(qr[d], Ks[j][d], acc);
            acc *= scale;
            if (diag && (jt * 64 + j > qi)) acc = -1e30f;
            S[j][row] = acc;
            mt = fmaxf(mt, acc);
        }

        const float mnew = fmaxf(m, mt);
        const float alpha = __expf(m - mnew);
        l *= alpha;
        #pragma unroll
        for (int d = 0; d < HDIM; ++d) O[d] *= alpha;

        for (int j = 0; j < 64; ++j) {
            const float p = __expf(S[j][row] - mnew);
            l += p;
            #pragma unroll
            for (int d = 0; d < HDIM; ++d) O[d] = fmaf(p, Vs[j][d], O[d]);
        }
        m = mnew;
    }

    const float inv = 1.f / l;
    float* obase = out + ((size_t)b * SEQ + qi) * CDIM + h * HDIM;
    #pragma unroll
    for (int d = 0; d < HDIM; ++d) obase[d] = O[d] * inv;
}

// ---------------------------------------------------------------------------
// Bridge head. y already sits at the start of d_out.
// Layout: y[4194304] | bridge_activated[2] | bridge_activations[204]
//
// bridge_idx dtype sniff: reference says int64 but JAX default (x64 disabled)
// makes it int32. If the buffer were int64 (values in [0,1024)), every odd
// int32 word would be 0; a 102-element distinct int32 permutation cannot have
// all 51 odd words zero. The sniff reads only the first 408 bytes (valid for
// both interpretations).
// ---------------------------------------------------------------------------
__global__ void bridge_kernel(const float* __restrict__ y,
                              const float* __restrict__ Wd,
                              const float* __restrict__ bd,
                              const int* __restrict__ idx32,
                              float* __restrict__ out)
{
    const int b = blockIdx.x;
    const int t = threadIdx.x;           // 128 threads
    __shared__ float red[128];
    __shared__ int is64;

    if (t == 0) {
        int z = 0;
        for (int i = 0; i < BSIZE / 2; ++i) z |= idx32[2 * i + 1];
        is64 = (z == 0) ? 1 : 0;
    }
    __syncthreads();

    float part = 0.f;
    if (t < BSIZE) {
        int c = is64 ? idx32[2 * t] : idx32[t];
        c &= (CDIM - 1);                 // hard safety clamp
        const float a = y[((size_t)b * SEQ + (SEQ - 1)) * CDIM + (size_t)c];
        out[(size_t)MROWS * CDIM + BATCH + b * BSIZE + t] = a;  // bridge_activations
        part = a * Wd[t];
    }
    red[t] = part;
    __syncthreads();
    for (int s = 64; s > 0; s >>= 1) {
        if (t < s) red[t] += red[t + s];
        __syncthreads();
    }
    if (t == 0) {
        const float sig = 1.f / (1.f + __expf(-(red[0] + bd[0])));
        out[(size_t)MROWS * CDIM + b] = (sig > 0.5f) ? 1.0f : 0.0f;  // bridge_activated
    }
}

// ---------------------------------------------------------------------------
extern "C" void kernel_launch(void* const* d_in, const int* in_sizes, int n_in,
                              void* d_out, int out_size)
{
    const float* x   = (const float*)d_in[0];
    const float* Wq  = (const float*)d_in[1];
    const float* bq  = (const float*)d_in[2];
    const float* Wk  = (const float*)d_in[3];
    const float* bk  = (const float*)d_in[4];
    const float* Wv  = (const float*)d_in[5];
    const float* bv  = (const float*)d_in[6];
    const float* Wp  = (const float*)d_in[7];
    const float* bp  = (const float*)d_in[8];
    const float* Wd  = (const float*)d_in[9];
    const float* bd  = (const float*)d_in[10];
    const int*   bidx = (const int*)d_in[11];
    float* out = (float*)d_out;

    float *gq, *gk, *gv, *gatt;
    cudaGetSymbolAddress((void**)&gq,  g_q);
    cudaGetSymbolAddress((void**)&gk,  g_k);
    cudaGetSymbolAddress((void**)&gv,  g_v);
    cudaGetSymbolAddress((void**)&gatt, g_att);

    dim3 ggrid(CDIM / 64, MROWS / 64);   // (16, 64)
    gemm64<<<ggrid, 256>>>(x, Wq, bq, gq, 0);
    gemm64<<<ggrid, 256>>>(x, Wk, bk, gk, 0);
    gemm64<<<ggrid, 256>>>(x, Wv, bv, gv, 0);

    attn_kernel<<<dim3(SEQ / 64, BATCH * NHEAD), 64>>>(gatt);

    gemm64<<<ggrid, 256>>>(gatt, Wp, bp, out, 1);

    bridge_kernel<<<BATCH, 128>>>(out, Wd, bd, bidx, out);
}

// round 3
// speedup vs baseline: 1.8360x; 1.8360x over previous
#include <cuda_runtime.h>
#include <cuda_bf16.h>
#include <cstdint>

// Problem constants
#define BATCH 2
#define SEQ   2048
#define CDIM  1024
#define NHEAD 16
#define HDIM  64
#define MROWS (BATCH*SEQ)      // 4096
#define BSIZE 102

// Scratch (device globals: allocation-free)
__device__ float g_q[BATCH*NHEAD*SEQ*HDIM];   // [B,H,T,D]
__device__ float g_k[BATCH*NHEAD*SEQ*HDIM];
__device__ float g_v[BATCH*NHEAD*SEQ*HDIM];
__device__ float g_att[MROWS*CDIM];           // [B,T,C]

// ---------------------------------------------------------------------------
// tf32 helpers
// ---------------------------------------------------------------------------
__device__ __forceinline__ float f2tf32(float f) {
    uint32_t r;
    asm("cvt.rna.tf32.f32 %0, %1;" : "=r"(r) : "f"(f));
    return __uint_as_float(r);
}

#define MMA_TF32(c0,c1,c2,c3,a0,a1,a2,a3,b0,b1)                          \
    asm volatile("mma.sync.aligned.m16n8k8.row.col.f32.tf32.tf32.f32 "  \
                 "{%0,%1,%2,%3},{%4,%5,%6,%7},{%8,%9},{%0,%1,%2,%3};"   \
                 : "+f"(c0), "+f"(c1), "+f"(c2), "+f"(c3)               \
                 : "r"(a0), "r"(a1), "r"(a2), "r"(a3), "r"(b0), "r"(b1))

// ---------------------------------------------------------------------------
// tf32 tensor-core GEMM: C[M,N] = A[M,K] @ W[K,N] + bias
// M=4096, N=K=1024. CTA tile 128x128, K-tile 32, 8 warps, warp tile 64x32.
// mode 0: scatter output into [B,H,T,D] layout (for q/k/v)
// mode 1: plain row-major [M,N]
// ---------------------------------------------------------------------------
#define BM 128
#define BN 128
#define BK 32
#define AS_LD (BK + 4)     // 36 floats: frag banks (4g+tg) distinct
#define BS_LD (BN + 8)     // 136 floats: frag banks (8tg+g) distinct

__global__ __launch_bounds__(256)
void gemm_tf32(const float* __restrict__ A, const float* __restrict__ W,
               const float* __restrict__ bias, float* __restrict__ C, int mode)
{
    const int K = CDIM, N = CDIM;
    __shared__ float As[BM][AS_LD];
    __shared__ float Bs[BK][BS_LD];

    const int tid  = threadIdx.x;
    const int rowBase = blockIdx.y * BM;
    const int colBase = blockIdx.x * BN;

    const int w    = tid >> 5;
    const int lane = tid & 31;
    const int g    = lane >> 2;        // 0..7
    const int tg   = lane & 3;         // 0..3
    const int wm   = (w >> 2) * 64;    // 0 or 64
    const int wn   = (w & 3) * 32;     // 0,32,64,96

    // global->reg load mappings (4 float4 each for A and B per thread)
    // A: 128 rows x 8 float4/row -> flat f = tid + i*256; row=f>>3, kc=(f&7)*4
    // B: 32 rows x 32 float4/row -> flat f = tid + i*256; kr=f>>5, nc=(f&31)*4
    float4 pa[4], pb[4];

    const float4* Ag = reinterpret_cast<const float4*>(A);
    const float4* Wg = reinterpret_cast<const float4*>(W);

    // prefetch tile 0
    #pragma unroll
    for (int i = 0; i < 4; ++i) {
        const int f = tid + i * 256;
        pa[i] = Ag[((size_t)(rowBase + (f >> 3)) * K + ((f & 7) << 2)) >> 2];
        pb[i] = Wg[((size_t)(f >> 5) * N + colBase + ((f & 31) << 2)) >> 2];
    }

    float c[4][4][4] = {};

    const int ntiles = K / BK;
    for (int kt = 0; kt < ntiles; ++kt) {
        __syncthreads();
        // stage prefetched tile into smem (with tf32 rounding)
        #pragma unroll
        for (int i = 0; i < 4; ++i) {
            const int f = tid + i * 256;
            float4 a = pa[i];
            a.x = f2tf32(a.x); a.y = f2tf32(a.y); a.z = f2tf32(a.z); a.w = f2tf32(a.w);
            *reinterpret_cast<float4*>(&As[f >> 3][(f & 7) << 2]) = a;
            float4 b = pb[i];
            b.x = f2tf32(b.x); b.y = f2tf32(b.y); b.z = f2tf32(b.z); b.w = f2tf32(b.w);
            *reinterpret_cast<float4*>(&Bs[f >> 5][(f & 31) << 2]) = b;
        }
        __syncthreads();

        // prefetch next tile while computing this one
        if (kt + 1 < ntiles) {
            const int k0 = (kt + 1) * BK;
            #pragma unroll
            for (int i = 0; i < 4; ++i) {
                const int f = tid + i * 256;
                pa[i] = Ag[((size_t)(rowBase + (f >> 3)) * K + k0 + ((f & 7) << 2)) >> 2];
                pb[i] = Wg[((size_t)(k0 + (f >> 5)) * N + colBase + ((f & 31) << 2)) >> 2];
            }
        }

        #pragma unroll
        for (int ks = 0; ks < BK / 8; ++ks) {
            const int kb = ks * 8;
            uint32_t af[4][4];
            #pragma unroll
            for (int mi = 0; mi < 4; ++mi) {
                const int r0 = wm + mi * 16 + g;
                af[mi][0] = __float_as_uint(As[r0    ][kb + tg]);
                af[mi][1] = __float_as_uint(As[r0 + 8][kb + tg]);
                af[mi][2] = __float_as_uint(As[r0    ][kb + tg + 4]);
                af[mi][3] = __float_as_uint(As[r0 + 8][kb + tg + 4]);
            }
            uint32_t bf[4][2];
            #pragma unroll
            for (int ni = 0; ni < 4; ++ni) {
                const int n0 = wn + ni * 8 + g;
                bf[ni][0] = __float_as_uint(Bs[kb + tg    ][n0]);
                bf[ni][1] = __float_as_uint(Bs[kb + tg + 4][n0]);
            }
            #pragma unroll
            for (int mi = 0; mi < 4; ++mi)
                #pragma unroll
                for (int ni = 0; ni < 4; ++ni)
                    MMA_TF32(c[mi][ni][0], c[mi][ni][1], c[mi][ni][2], c[mi][ni][3],
                             af[mi][0], af[mi][1], af[mi][2], af[mi][3],
                             bf[ni][0], bf[ni][1]);
        }
    }

    // epilogue: c[mi][ni][e] -> (row, col)
    //   row = rowBase + wm + mi*16 + g + (e>=2 ? 8 : 0)
    //   col = colBase + wn + ni*8 + 2*tg + (e&1)
    #pragma unroll
    for (int mi = 0; mi < 4; ++mi) {
        #pragma unroll
        for (int ni = 0; ni < 4; ++ni) {
            #pragma unroll
            for (int e = 0; e < 4; ++e) {
                const int r = rowBase + wm + mi * 16 + g + ((e >> 1) << 3);
                const int cc = colBase + wn + ni * 8 + 2 * tg + (e & 1);
                const float val = c[mi][ni][e] + bias[cc];
                if (mode == 0) {
                    const int b = r >> 11;
                    const int t = r & (SEQ - 1);
                    const int h = cc >> 6;
                    const int d = cc & (HDIM - 1);
                    C[(((size_t)b * NHEAD + h) * SEQ + t) * HDIM + d] = val;
                } else {
                    C[(size_t)r * CDIM + cc] = val;
                }
            }
        }
    }
}

// ---------------------------------------------------------------------------
// Causal flash attention. grid = (T/128, B*H), block = 128 threads.
// Each thread owns one query row; K/V tiles (32 keys) in smem, float4
// broadcast reads (1 LDS.128 : 4 FMA). S scores staged in smem column-per-
// thread. Heavy query tiles scheduled first. Writes [B,T,C].
// ---------------------------------------------------------------------------
#define QT 128
#define JT 32

__global__ __launch_bounds__(128)
void attn_kernel(float* __restrict__ out)
{
    const int qt  = gridDim.x - 1 - blockIdx.x;   // heavy tiles first
    const int bh  = blockIdx.y;
    const int b   = bh >> 4;
    const int h   = bh & 15;
    const int t   = threadIdx.x;                  // 0..127
    const int qi  = qt * QT + t;

    __shared__ float Ks[JT][HDIM];
    __shared__ float Vs[JT][HDIM];
    __shared__ float S[JT][QT];

    const float4* qbase = reinterpret_cast<const float4*>(
        g_q + ((size_t)bh * SEQ + qi) * HDIM);
    float4 q4[16];
    #pragma unroll
    for (int i = 0; i < 16; ++i) q4[i] = qbase[i];

    float4 o4[16];
    #pragma unroll
    for (int i = 0; i < 16; ++i) o4[i] = make_float4(0.f, 0.f, 0.f, 0.f);
    float m = -1e30f, l = 0.f;

    const float scale = 0.125f;
    const float* kt0 = g_k + (size_t)bh * SEQ * HDIM;
    const float* vt0 = g_v + (size_t)bh * SEQ * HDIM;

    const int njt = qt * (QT / JT) + (QT / JT);   // tiles up to causal edge

    for (int jt = 0; jt < njt; ++jt) {
        const int j0 = jt * JT;
        __syncthreads();
        // load 32x64 K and V tiles: 512 float4 each / 128 thr = 4 each
        {
            const float4* kg = reinterpret_cast<const float4*>(kt0 + (size_t)j0 * HDIM);
            const float4* vg = reinterpret_cast<const float4*>(vt0 + (size_t)j0 * HDIM);
            #pragma unroll
            for (int u = 0; u < 4; ++u) {
                const int f = t + u * 128;        // 0..511
                const int r = f >> 4;
                const int cidx = f & 15;
                *reinterpret_cast<float4*>(&Ks[r][cidx << 2]) = kg[(size_t)r * 16 + cidx];
                *reinterpret_cast<float4*>(&Vs[r][cidx << 2]) = vg[(size_t)r * 16 + cidx];
            }
        }
        __syncthreads();

        const bool edge = (j0 + JT - 1 > qi);
        float mt = m;
        #pragma unroll 4
        for (int j = 0; j < JT; ++j) {
            float a0 = 0.f, a1 = 0.f, a2 = 0.f, a3 = 0.f;
            #pragma unroll
            for (int du = 0; du < 16; ++du) {
                const float4 kv = *reinterpret_cast<const float4*>(&Ks[j][du << 2]);
                a0 = fmaf(q4[du].x, kv.x, a0);
                a1 = fmaf(q4[du].y, kv.y, a1);
                a2 = fmaf(q4[du].z, kv.z, a2);
                a3 = fmaf(q4[du].w, kv.w, a3);
            }
            float acc = ((a0 + a1) + (a2 + a3)) * scale;
            if (edge && (j0 + j > qi)) acc = -1e30f;
            S[j][t] = acc;
            mt = fmaxf(mt, acc);
        }

        const float alpha = __expf(m - mt);
        l *= alpha;
        #pragma unroll
        for (int du = 0; du < 16; ++du) {
            o4[du].x *= alpha; o4[du].y *= alpha; o4[du].z *= alpha; o4[du].w *= alpha;
        }

        #pragma unroll 4
        for (int j = 0; j < JT; ++j) {
            const float p = __expf(S[j][t] - mt);
            l += p;
            #pragma unroll
            for (int du = 0; du < 16; ++du) {
                const float4 vv = *reinterpret_cast<const float4*>(&Vs[j][du << 2]);
                o4[du].x = fmaf(p, vv.x, o4[du].x);
                o4[du].y = fmaf(p, vv.y, o4[du].y);
                o4[du].z = fmaf(p, vv.z, o4[du].z);
                o4[du].w = fmaf(p, vv.w, o4[du].w);
            }
        }
        m = mt;
    }

    const float inv = 1.f / l;
    float4* obase = reinterpret_cast<float4*>(
        out + ((size_t)b * SEQ + qi) * CDIM + h * HDIM);
    #pragma unroll
    for (int du = 0; du < 16; ++du) {
        float4 v = o4[du];
        v.x *= inv; v.y *= inv; v.z *= inv; v.w *= inv;
        obase[du] = v;
    }
}

// ---------------------------------------------------------------------------
// Bridge head. y already sits at the start of d_out.
// Layout: y[4194304] | bridge_activated[2] | bridge_activations[204]
// bridge_idx dtype sniff (int32 vs int64) as before.
// ---------------------------------------------------------------------------
__global__ void bridge_kernel(const float* __restrict__ y,
                              const float* __restrict__ Wd,
                              const float* __restrict__ bd,
                              const int* __restrict__ idx32,
                              float* __restrict__ out)
{
    const int b = blockIdx.x;
    const int t = threadIdx.x;           // 128 threads
    __shared__ float red[128];
    __shared__ int is64;

    if (t == 0) {
        int z = 0;
        for (int i = 0; i < BSIZE / 2; ++i) z |= idx32[2 * i + 1];
        is64 = (z == 0) ? 1 : 0;
    }
    __syncthreads();

    float part = 0.f;
    if (t < BSIZE) {
        int c = is64 ? idx32[2 * t] : idx32[t];
        c &= (CDIM - 1);                 // hard safety clamp
        const float a = y[((size_t)b * SEQ + (SEQ - 1)) * CDIM + (size_t)c];
        out[(size_t)MROWS * CDIM + BATCH + b * BSIZE + t] = a;  // bridge_activations
        part = a * Wd[t];
    }
    red[t] = part;
    __syncthreads();
    for (int s = 64; s > 0; s >>= 1) {
        if (t < s) red[t] += red[t + s];
        __syncthreads();
    }
    if (t == 0) {
        const float sig = 1.f / (1.f + __expf(-(red[0] + bd[0])));
        out[(size_t)MROWS * CDIM + b] = (sig > 0.5f) ? 1.0f : 0.0f;  // bridge_activated
    }
}

// ---------------------------------------------------------------------------
extern "C" void kernel_launch(void* const* d_in, const int* in_sizes, int n_in,
                              void* d_out, int out_size)
{
    const float* x   = (const float*)d_in[0];
    const float* Wq  = (const float*)d_in[1];
    const float* bq  = (const float*)d_in[2];
    const float* Wk  = (const float*)d_in[3];
    const float* bk  = (const float*)d_in[4];
    const float* Wv  = (const float*)d_in[5];
    const float* bv  = (const float*)d_in[6];
    const float* Wp  = (const float*)d_in[7];
    const float* bp  = (const float*)d_in[8];
    const float* Wd  = (const float*)d_in[9];
    const float* bd  = (const float*)d_in[10];
    const int*   bidx = (const int*)d_in[11];
    float* out = (float*)d_out;

    float *gq, *gk, *gv, *gatt;
    cudaGetSymbolAddress((void**)&gq,  g_q);
    cudaGetSymbolAddress((void**)&gk,  g_k);
    cudaGetSymbolAddress((void**)&gv,  g_v);
    cudaGetSymbolAddress((void**)&gatt, g_att);

    dim3 ggrid(CDIM / BN, MROWS / BM);   // (8, 32)
    gemm_tf32<<<ggrid, 256>>>(x, Wq, bq, gq, 0);
    gemm_tf32<<<ggrid, 256>>>(x, Wk, bk, gk, 0);
    gemm_tf32<<<ggrid, 256>>>(x, Wv, bv, gv, 0);

    attn_kernel<<<dim3(SEQ / QT, BATCH * NHEAD), 128>>>(gatt);

    gemm_tf32<<<ggrid, 256>>>(gatt, Wp, bp, out, 1);

    bridge_kernel<<<BATCH, 128>>>(out, Wd, bd, bidx, out);
}

// round 4
// speedup vs baseline: 3.8952x; 2.1216x over previous
#include <cuda_runtime.h>
#include <cuda_bf16.h>
#include <cstdint>

// Problem constants
#define BATCH 2
#define SEQ   2048
#define CDIM  1024
#define NHEAD 16
#define HDIM  64
#define MROWS (BATCH*SEQ)      // 4096
#define BSIZE 102

// Scratch (device globals: allocation-free)
__device__ float g_q[BATCH*NHEAD*SEQ*HDIM];   // [B,H,T,D]
__device__ float g_k[BATCH*NHEAD*SEQ*HDIM];
__device__ float g_v[BATCH*NHEAD*SEQ*HDIM];
__device__ float g_att[MROWS*CDIM];           // [B,T,C]

// ---------------------------------------------------------------------------
// tf32 helpers
// ---------------------------------------------------------------------------
__device__ __forceinline__ float f2tf32(float f) {
    uint32_t r;
    asm("cvt.rna.tf32.f32 %0, %1;" : "=r"(r) : "f"(f));
    return __uint_as_float(r);
}
__device__ __forceinline__ uint32_t tf32u(float f) {
    uint32_t r;
    asm("cvt.rna.tf32.f32 %0, %1;" : "=r"(r) : "f"(f));
    return r;
}

#define MMA_TF32(c0,c1,c2,c3,a0,a1,a2,a3,b0,b1)                          \
    asm volatile("mma.sync.aligned.m16n8k8.row.col.f32.tf32.tf32.f32 "  \
                 "{%0,%1,%2,%3},{%4,%5,%6,%7},{%8,%9},{%0,%1,%2,%3};"   \
                 : "+f"(c0), "+f"(c1), "+f"(c2), "+f"(c3)               \
                 : "r"(a0), "r"(a1), "r"(a2), "r"(a3), "r"(b0), "r"(b1))

// ---------------------------------------------------------------------------
// tf32 tensor-core GEMM: C[M,N] = A[M,K] @ W[K,N] + bias
// M=4096, N=K=1024. CTA tile 128x128, K-tile 32, 8 warps, warp tile 64x32.
// mode 0: scatter output into [B,H,T,D] layout (for q/k/v)
// mode 1: plain row-major [M,N]
// ---------------------------------------------------------------------------
#define BM 128
#define BN 128
#define BK 32
#define AS_LD (BK + 4)     // 36 floats
#define BS_LD (BN + 8)     // 136 floats

__global__ __launch_bounds__(256)
void gemm_tf32(const float* __restrict__ A, const float* __restrict__ W,
               const float* __restrict__ bias, float* __restrict__ C, int mode)
{
    const int K = CDIM, N = CDIM;
    __shared__ float As[BM][AS_LD];
    __shared__ float Bs[BK][BS_LD];

    const int tid  = threadIdx.x;
    const int rowBase = blockIdx.y * BM;
    const int colBase = blockIdx.x * BN;

    const int w    = tid >> 5;
    const int lane = tid & 31;
    const int g    = lane >> 2;
    const int tg   = lane & 3;
    const int wm   = (w >> 2) * 64;
    const int wn   = (w & 3) * 32;

    float4 pa[4], pb[4];
    const float4* Ag = reinterpret_cast<const float4*>(A);
    const float4* Wg = reinterpret_cast<const float4*>(W);

    #pragma unroll
    for (int i = 0; i < 4; ++i) {
        const int f = tid + i * 256;
        pa[i] = Ag[((size_t)(rowBase + (f >> 3)) * K + ((f & 7) << 2)) >> 2];
        pb[i] = Wg[((size_t)(f >> 5) * N + colBase + ((f & 31) << 2)) >> 2];
    }

    float c[4][4][4] = {};

    const int ntiles = K / BK;
    for (int kt = 0; kt < ntiles; ++kt) {
        __syncthreads();
        #pragma unroll
        for (int i = 0; i < 4; ++i) {
            const int f = tid + i * 256;
            float4 a = pa[i];
            a.x = f2tf32(a.x); a.y = f2tf32(a.y); a.z = f2tf32(a.z); a.w = f2tf32(a.w);
            *reinterpret_cast<float4*>(&As[f >> 3][(f & 7) << 2]) = a;
            float4 b = pb[i];
            b.x = f2tf32(b.x); b.y = f2tf32(b.y); b.z = f2tf32(b.z); b.w = f2tf32(b.w);
            *reinterpret_cast<float4*>(&Bs[f >> 5][(f & 31) << 2]) = b;
        }
        __syncthreads();

        if (kt + 1 < ntiles) {
            const int k0 = (kt + 1) * BK;
            #pragma unroll
            for (int i = 0; i < 4; ++i) {
                const int f = tid + i * 256;
                pa[i] = Ag[((size_t)(rowBase + (f >> 3)) * K + k0 + ((f & 7) << 2)) >> 2];
                pb[i] = Wg[((size_t)(k0 + (f >> 5)) * N + colBase + ((f & 31) << 2)) >> 2];
            }
        }

        #pragma unroll
        for (int ks = 0; ks < BK / 8; ++ks) {
            const int kb = ks * 8;
            uint32_t af[4][4];
            #pragma unroll
            for (int mi = 0; mi < 4; ++mi) {
                const int r0 = wm + mi * 16 + g;
                af[mi][0] = __float_as_uint(As[r0    ][kb + tg]);
                af[mi][1] = __float_as_uint(As[r0 + 8][kb + tg]);
                af[mi][2] = __float_as_uint(As[r0    ][kb + tg + 4]);
                af[mi][3] = __float_as_uint(As[r0 + 8][kb + tg + 4]);
            }
            uint32_t bf[4][2];
            #pragma unroll
            for (int ni = 0; ni < 4; ++ni) {
                const int n0 = wn + ni * 8 + g;
                bf[ni][0] = __float_as_uint(Bs[kb + tg    ][n0]);
                bf[ni][1] = __float_as_uint(Bs[kb + tg + 4][n0]);
            }
            #pragma unroll
            for (int mi = 0; mi < 4; ++mi)
                #pragma unroll
                for (int ni = 0; ni < 4; ++ni)
                    MMA_TF32(c[mi][ni][0], c[mi][ni][1], c[mi][ni][2], c[mi][ni][3],
                             af[mi][0], af[mi][1], af[mi][2], af[mi][3],
                             bf[ni][0], bf[ni][1]);
        }
    }

    #pragma unroll
    for (int mi = 0; mi < 4; ++mi) {
        #pragma unroll
        for (int ni = 0; ni < 4; ++ni) {
            #pragma unroll
            for (int e = 0; e < 4; ++e) {
                const int r = rowBase + wm + mi * 16 + g + ((e >> 1) << 3);
                const int cc = colBase + wn + ni * 8 + 2 * tg + (e & 1);
                const float val = c[mi][ni][e] + bias[cc];
                if (mode == 0) {
                    const int b = r >> 11;
                    const int t = r & (SEQ - 1);
                    const int h = cc >> 6;
                    const int d = cc & (HDIM - 1);
                    C[(((size_t)b * NHEAD + h) * SEQ + t) * HDIM + d] = val;
                } else {
                    C[(size_t)r * CDIM + cc] = val;
                }
            }
        }
    }
}

// ---------------------------------------------------------------------------
// Tensor-core causal flash attention (tf32).
// grid = (SEQ/128, B*H), block = 256 (8 warps x 16 query rows).
// Key tile = 64. K/V in smem stride 68 (conflict-free for both B-frag
// patterns). Q frags in registers; softmax in registers; P C-frag -> A-frag
// via shuffles. Heavy query tiles scheduled first. Writes [B,T,C].
// ---------------------------------------------------------------------------
#define KV_LD 68

__global__ __launch_bounds__(256)
void attn_tc(float* __restrict__ out)
{
    const int qt   = gridDim.x - 1 - blockIdx.x;   // heavy tiles first
    const int bh   = blockIdx.y;
    const int b    = bh >> 4;
    const int h    = bh & 15;
    const int tid  = threadIdx.x;
    const int warp = tid >> 5;
    const int lane = tid & 31;
    const int g    = lane >> 2;
    const int tg   = lane & 3;
    const int q0   = qt * 128;
    const int row_base = q0 + warp * 16;

    __shared__ float Ks[64][KV_LD];
    __shared__ float Vs[64][KV_LD];

    // Q fragments (1/8 scale folded in; exact, power of two)
    const float* qp = g_q + ((size_t)bh * SEQ + row_base) * HDIM;
    uint32_t Qa[8][4];
    #pragma unroll
    for (int kb = 0; kb < 8; ++kb) {
        Qa[kb][0] = tf32u(0.125f * qp[(size_t)g        * 64 + kb * 8 + tg]);
        Qa[kb][1] = tf32u(0.125f * qp[(size_t)(g + 8)  * 64 + kb * 8 + tg]);
        Qa[kb][2] = tf32u(0.125f * qp[(size_t)g        * 64 + kb * 8 + tg + 4]);
        Qa[kb][3] = tf32u(0.125f * qp[(size_t)(g + 8)  * 64 + kb * 8 + tg + 4]);
    }

    float O[8][4];
    #pragma unroll
    for (int nb = 0; nb < 8; ++nb)
        #pragma unroll
        for (int e = 0; e < 4; ++e) O[nb][e] = 0.f;
    float m0 = -1e30f, m1 = -1e30f, l0 = 0.f, l1 = 0.f;

    const float* kt0 = g_k + (size_t)bh * SEQ * HDIM;
    const float* vt0 = g_v + (size_t)bh * SEQ * HDIM;

    const int njt = 2 * qt + 2;

    for (int jt = 0; jt < njt; ++jt) {
        const int j0 = jt * 64;
        __syncthreads();
        // stage 64x64 K and V (tf32-rounded): 1024 float4 each / 256 thr
        {
            const float4* kg = reinterpret_cast<const float4*>(kt0 + (size_t)j0 * HDIM);
            const float4* vg = reinterpret_cast<const float4*>(vt0 + (size_t)j0 * HDIM);
            #pragma unroll
            for (int u = 0; u < 4; ++u) {
                const int f = tid + u * 256;     // 0..1023
                const int r = f >> 4;
                const int cI = f & 15;
                float4 k4 = kg[(size_t)r * 16 + cI];
                k4.x = f2tf32(k4.x); k4.y = f2tf32(k4.y);
                k4.z = f2tf32(k4.z); k4.w = f2tf32(k4.w);
                *reinterpret_cast<float4*>(&Ks[r][cI << 2]) = k4;
                float4 v4 = vg[(size_t)r * 16 + cI];
                v4.x = f2tf32(v4.x); v4.y = f2tf32(v4.y);
                v4.z = f2tf32(v4.z); v4.w = f2tf32(v4.w);
                *reinterpret_cast<float4*>(&Vs[r][cI << 2]) = v4;
            }
        }
        __syncthreads();

        // S = Q @ K^T  (keys as n)
        float s[8][4];
        #pragma unroll
        for (int nb = 0; nb < 8; ++nb)
            #pragma unroll
            for (int e = 0; e < 4; ++e) s[nb][e] = 0.f;

        #pragma unroll
        for (int kb = 0; kb < 8; ++kb) {
            #pragma unroll
            for (int nb = 0; nb < 8; ++nb) {
                const uint32_t b0 = __float_as_uint(Ks[nb * 8 + g][kb * 8 + tg]);
                const uint32_t b1 = __float_as_uint(Ks[nb * 8 + g][kb * 8 + tg + 4]);
                MMA_TF32(s[nb][0], s[nb][1], s[nb][2], s[nb][3],
                         Qa[kb][0], Qa[kb][1], Qa[kb][2], Qa[kb][3], b0, b1);
            }
        }

        // causal mask (only last two tiles can cross the diagonal)
        if (jt >= njt - 2) {
            #pragma unroll
            for (int nb = 0; nb < 8; ++nb) {
                #pragma unroll
                for (int e = 0; e < 4; ++e) {
                    const int col = j0 + nb * 8 + 2 * tg + (e & 1);
                    const int row = row_base + g + ((e >> 1) << 3);
                    if (col > row) s[nb][e] = -1e30f;
                }
            }
        }

        // online softmax
        float mt0 = m0, mt1 = m1;
        #pragma unroll
        for (int nb = 0; nb < 8; ++nb) {
            mt0 = fmaxf(mt0, fmaxf(s[nb][0], s[nb][1]));
            mt1 = fmaxf(mt1, fmaxf(s[nb][2], s[nb][3]));
        }
        mt0 = fmaxf(mt0, __shfl_xor_sync(0xffffffff, mt0, 1));
        mt0 = fmaxf(mt0, __shfl_xor_sync(0xffffffff, mt0, 2));
        mt1 = fmaxf(mt1, __shfl_xor_sync(0xffffffff, mt1, 1));
        mt1 = fmaxf(mt1, __shfl_xor_sync(0xffffffff, mt1, 2));

        const float al0 = __expf(m0 - mt0);
        const float al1 = __expf(m1 - mt1);
        l0 *= al0; l1 *= al1; m0 = mt0; m1 = mt1;
        #pragma unroll
        for (int nb = 0; nb < 8; ++nb) {
            O[nb][0] *= al0; O[nb][1] *= al0;
            O[nb][2] *= al1; O[nb][3] *= al1;
        }

        // P = exp(S - m); convert C-frag -> A-frag via shuffles; O += P @ V
        const int srcA = (lane & ~3) | (tg >> 1);
        const int srcB = srcA | 2;
        #pragma unroll
        for (int kb = 0; kb < 8; ++kb) {
            const float p0 = __expf(s[kb][0] - m0);
            const float p1 = __expf(s[kb][1] - m0);
            const float p2 = __expf(s[kb][2] - m1);
            const float p3 = __expf(s[kb][3] - m1);
            l0 += p0 + p1;
            l1 += p2 + p3;
            const float r0 = f2tf32(p0), r1 = f2tf32(p1);
            const float r2 = f2tf32(p2), r3 = f2tf32(p3);

            const float x0A = __shfl_sync(0xffffffff, r0, srcA);
            const float x1A = __shfl_sync(0xffffffff, r1, srcA);
            const float x0B = __shfl_sync(0xffffffff, r0, srcB);
            const float x1B = __shfl_sync(0xffffffff, r1, srcB);
            const float y0A = __shfl_sync(0xffffffff, r2, srcA);
            const float y1A = __shfl_sync(0xffffffff, r3, srcA);
            const float y0B = __shfl_sync(0xffffffff, r2, srcB);
            const float y1B = __shfl_sync(0xffffffff, r3, srcB);

            const uint32_t pa0 = __float_as_uint((tg & 1) ? x1A : x0A);
            const uint32_t pa1 = __float_as_uint((tg & 1) ? y1A : y0A);
            const uint32_t pa2 = __float_as_uint((tg & 1) ? x1B : x0B);
            const uint32_t pa3 = __float_as_uint((tg & 1) ? y1B : y0B);

            #pragma unroll
            for (int nb = 0; nb < 8; ++nb) {
                const uint32_t b0 = __float_as_uint(Vs[kb * 8 + tg    ][nb * 8 + g]);
                const uint32_t b1 = __float_as_uint(Vs[kb * 8 + tg + 4][nb * 8 + g]);
                MMA_TF32(O[nb][0], O[nb][1], O[nb][2], O[nb][3],
                         pa0, pa1, pa2, pa3, b0, b1);
            }
        }
    }

    // final l reduction across quad
    l0 += __shfl_xor_sync(0xffffffff, l0, 1);
    l0 += __shfl_xor_sync(0xffffffff, l0, 2);
    l1 += __shfl_xor_sync(0xffffffff, l1, 1);
    l1 += __shfl_xor_sync(0xffffffff, l1, 2);
    const float inv0 = 1.f / l0;
    const float inv1 = 1.f / l1;

    float* orow0 = out + ((size_t)b * SEQ + row_base + g    ) * CDIM + h * 64;
    float* orow1 = out + ((size_t)b * SEQ + row_base + g + 8) * CDIM + h * 64;
    #pragma unroll
    for (int nb = 0; nb < 8; ++nb) {
        const int cc = nb * 8 + 2 * tg;
        *reinterpret_cast<float2*>(orow0 + cc) =
            make_float2(O[nb][0] * inv0, O[nb][1] * inv0);
        *reinterpret_cast<float2*>(orow1 + cc) =
            make_float2(O[nb][2] * inv1, O[nb][3] * inv1);
    }
}

// ---------------------------------------------------------------------------
// Bridge head. y already sits at the start of d_out.
// Layout: y[4194304] | bridge_activated[2] | bridge_activations[204]
// bridge_idx dtype sniff (int32 vs int64) as before.
// ---------------------------------------------------------------------------
__global__ void bridge_kernel(const float* __restrict__ y,
                              const float* __restrict__ Wd,
                              const float* __restrict__ bd,
                              const int* __restrict__ idx32,
                              float* __restrict__ out)
{
    const int b = blockIdx.x;
    const int t = threadIdx.x;           // 128 threads
    __shared__ float red[128];
    __shared__ int is64;

    if (t == 0) {
        int z = 0;
        for (int i = 0; i < BSIZE / 2; ++i) z |= idx32[2 * i + 1];
        is64 = (z == 0) ? 1 : 0;
    }
    __syncthreads();

    float part = 0.f;
    if (t < BSIZE) {
        int c = is64 ? idx32[2 * t] : idx32[t];
        c &= (CDIM - 1);                 // hard safety clamp
        const float a = y[((size_t)b * SEQ + (SEQ - 1)) * CDIM + (size_t)c];
        out[(size_t)MROWS * CDIM + BATCH + b * BSIZE + t] = a;  // bridge_activations
        part = a * Wd[t];
    }
    red[t] = part;
    __syncthreads();
    for (int s = 64; s > 0; s >>= 1) {
        if (t < s) red[t] += red[t + s];
        __syncthreads();
    }
    if (t == 0) {
        const float sig = 1.f / (1.f + __expf(-(red[0] + bd[0])));
        out[(size_t)MROWS * CDIM + b] = (sig > 0.5f) ? 1.0f : 0.0f;  // bridge_activated
    }
}

// ---------------------------------------------------------------------------
extern "C" void kernel_launch(void* const* d_in, const int* in_sizes, int n_in,
                              void* d_out, int out_size)
{
    const float* x   = (const float*)d_in[0];
    const float* Wq  = (const float*)d_in[1];
    const float* bq  = (const float*)d_in[2];
    const float* Wk  = (const float*)d_in[3];
    const float* bk  = (const float*)d_in[4];
    const float* Wv  = (const float*)d_in[5];
    const float* bv  = (const float*)d_in[6];
    const float* Wp  = (const float*)d_in[7];
    const float* bp  = (const float*)d_in[8];
    const float* Wd  = (const float*)d_in[9];
    const float* bd  = (const float*)d_in[10];
    const int*   bidx = (const int*)d_in[11];
    float* out = (float*)d_out;

    float *gq, *gk, *gv, *gatt;
    cudaGetSymbolAddress((void**)&gq,  g_q);
    cudaGetSymbolAddress((void**)&gk,  g_k);
    cudaGetSymbolAddress((void**)&gv,  g_v);
    cudaGetSymbolAddress((void**)&gatt, g_att);

    dim3 ggrid(CDIM / BN, MROWS / BM);   // (8, 32)
    gemm_tf32<<<ggrid, 256>>>(x, Wq, bq, gq, 0);
    gemm_tf32<<<ggrid, 256>>>(x, Wk, bk, gk, 0);
    gemm_tf32<<<ggrid, 256>>>(x, Wv, bv, gv, 0);

    attn_tc<<<dim3(SEQ / 128, BATCH * NHEAD), 256>>>(gatt);

    gemm_tf32<<<ggrid, 256>>>(gatt, Wp, bp, out, 1);

    bridge_kernel<<<BATCH, 128>>>(out, Wd, bd, bidx, out);
}

// round 5
// speedup vs baseline: 4.5631x; 1.1715x over previous
#include <cuda_runtime.h>
#include <cuda_bf16.h>
#include <cstdint>

// Problem constants
#define BATCH 2
#define SEQ   2048
#define CDIM  1024
#define NHEAD 16
#define HDIM  64
#define MROWS (BATCH*SEQ)      // 4096
#define BSIZE 102

// Scratch (device globals: allocation-free)
__device__ float g_q[BATCH*NHEAD*SEQ*HDIM];   // [B,H,T,D]
__device__ float g_k[BATCH*NHEAD*SEQ*HDIM];
__device__ float g_v[BATCH*NHEAD*SEQ*HDIM];
__device__ float g_att[MROWS*CDIM];           // [B,T,C]

// ---------------------------------------------------------------------------
// helpers
// ---------------------------------------------------------------------------
__device__ __forceinline__ float f2tf32(float f) {
    uint32_t r;
    asm("cvt.rna.tf32.f32 %0, %1;" : "=r"(r) : "f"(f));
    return __uint_as_float(r);
}
__device__ __forceinline__ uint32_t tf32u(float f) {
    uint32_t r;
    asm("cvt.rna.tf32.f32 %0, %1;" : "=r"(r) : "f"(f));
    return r;
}

#define MMA_TF32(c0,c1,c2,c3,a0,a1,a2,a3,b0,b1)                          \
    asm volatile("mma.sync.aligned.m16n8k8.row.col.f32.tf32.tf32.f32 "  \
                 "{%0,%1,%2,%3},{%4,%5,%6,%7},{%8,%9},{%0,%1,%2,%3};"   \
                 : "+f"(c0), "+f"(c1), "+f"(c2), "+f"(c3)               \
                 : "r"(a0), "r"(a1), "r"(a2), "r"(a3), "r"(b0), "r"(b1))

__device__ __forceinline__ void ldsm4(uint32_t& r0, uint32_t& r1,
                                      uint32_t& r2, uint32_t& r3,
                                      const void* p) {
    uint32_t s = (uint32_t)__cvta_generic_to_shared(p);
    asm volatile("ldmatrix.sync.aligned.m8n8.x4.shared.b16 {%0,%1,%2,%3}, [%4];"
                 : "=r"(r0), "=r"(r1), "=r"(r2), "=r"(r3) : "r"(s));
}

__device__ __forceinline__ void cp16(void* smem_dst, const void* gptr) {
    uint32_t s = (uint32_t)__cvta_generic_to_shared(smem_dst);
    asm volatile("cp.async.cg.shared.global [%0], [%1], 16;" :: "r"(s), "l"(gptr));
}
#define CP_COMMIT() asm volatile("cp.async.commit_group;")
#define CP_WAIT(n)  asm volatile("cp.async.wait_group %0;" :: "n"(n))

// ---------------------------------------------------------------------------
// tf32 tensor-core GEMM, cp.async double-buffered, ldmatrix A-frags.
// C[M,N] = A[M,K] @ W[K,N] + bias.  M=4096, N=K=1024.
// CTA 128x128, K-tile 32, 8 warps (64x32 warp tile).
// mode 0: scatter output into [B,H,T,D]; mode 1: row-major [M,N]
// ---------------------------------------------------------------------------
#define BM 128
#define BN 128
#define BK 32
#define AS_LD 36
#define BS_LD 136
#define AS_SZ (BM*AS_LD)                    // 4608 floats
#define BS_SZ (BK*BS_LD)                    // 4352 floats
#define GSMEM ((2*AS_SZ + 2*BS_SZ)*4)       // 71680 bytes

__global__ __launch_bounds__(256)
void gemm_tf32(const float* __restrict__ A, const float* __restrict__ W,
               const float* __restrict__ bias, float* __restrict__ C, int mode)
{
    const int K = CDIM, N = CDIM;
    extern __shared__ float sm[];
    float* As = sm;               // [2][BM][AS_LD]
    float* Bs = sm + 2 * AS_SZ;   // [2][BK][BS_LD]

    const int tid  = threadIdx.x;
    const int rowBase = blockIdx.y * BM;
    const int colBase = blockIdx.x * BN;

    const int w    = tid >> 5;
    const int lane = tid & 31;
    const int g    = lane >> 2;
    const int tg   = lane & 3;
    const int wm   = (w >> 2) * 64;
    const int wn   = (w & 3) * 32;

    // ldmatrix lane address components for A frags
    const int lm_row = ((lane >> 3) & 1) * 8 + (lane & 7);
    const int lm_col = (lane >> 4) * 4;

    float c[4][4][4] = {};
    const int ntiles = K / BK;

    // issue tile kt into buffer buf
    auto issue = [&](int buf, int kt) {
        const int k0 = kt * BK;
        #pragma unroll
        for (int i = 0; i < 4; ++i) {
            const int f = tid + i * 256;
            const int ar = f >> 3, ac = f & 7;           // 128 rows x 8 chunks
            cp16(&As[buf * AS_SZ + ar * AS_LD + ac * 4],
                 &A[(size_t)(rowBase + ar) * K + k0 + ac * 4]);
            const int br = f >> 5, bc = f & 31;          // 32 rows x 32 chunks
            cp16(&Bs[buf * BS_SZ + br * BS_LD + bc * 4],
                 &W[(size_t)(k0 + br) * N + colBase + bc * 4]);
        }
        CP_COMMIT();
    };

    int buf = 0;
    issue(0, 0);

    for (int kt = 0; kt < ntiles; ++kt) {
        if (kt + 1 < ntiles) {
            issue(buf ^ 1, kt + 1);
            CP_WAIT(1);
        } else {
            CP_WAIT(0);
        }
        __syncthreads();

        const float* Ab = As + buf * AS_SZ;
        const float* Bb = Bs + buf * BS_SZ;

        #pragma unroll
        for (int ks = 0; ks < BK / 8; ++ks) {
            const int kb = ks * 8;
            uint32_t af[4][4];
            #pragma unroll
            for (int mi = 0; mi < 4; ++mi) {
                const int r = wm + mi * 16 + lm_row;
                ldsm4(af[mi][0], af[mi][1], af[mi][2], af[mi][3],
                      &Ab[r * AS_LD + kb + lm_col]);
                #pragma unroll
                for (int j = 0; j < 4; ++j)
                    af[mi][j] = tf32u(__uint_as_float(af[mi][j]));
            }
            uint32_t bf[4][2];
            #pragma unroll
            for (int ni = 0; ni < 4; ++ni) {
                const int n0 = wn + ni * 8 + g;
                bf[ni][0] = tf32u(Bb[(kb + tg    ) * BS_LD + n0]);
                bf[ni][1] = tf32u(Bb[(kb + tg + 4) * BS_LD + n0]);
            }
            #pragma unroll
            for (int mi = 0; mi < 4; ++mi)
                #pragma unroll
                for (int ni = 0; ni < 4; ++ni)
                    MMA_TF32(c[mi][ni][0], c[mi][ni][1], c[mi][ni][2], c[mi][ni][3],
                             af[mi][0], af[mi][1], af[mi][2], af[mi][3],
                             bf[ni][0], bf[ni][1]);
        }
        __syncthreads();
        buf ^= 1;
    }

    #pragma unroll
    for (int mi = 0; mi < 4; ++mi) {
        #pragma unroll
        for (int ni = 0; ni < 4; ++ni) {
            #pragma unroll
            for (int e = 0; e < 4; ++e) {
                const int r  = rowBase + wm + mi * 16 + g + ((e >> 1) << 3);
                const int cc = colBase + wn + ni * 8 + 2 * tg + (e & 1);
                const float val = c[mi][ni][e] + bias[cc];
                if (mode == 0) {
                    const int b = r >> 11;
                    const int t = r & (SEQ - 1);
                    const int h = cc >> 6;
                    const int d = cc & (HDIM - 1);
                    C[(((size_t)b * NHEAD + h) * SEQ + t) * HDIM + d] = val;
                } else {
                    C[(size_t)r * CDIM + cc] = val;
                }
            }
        }
    }
}

// ---------------------------------------------------------------------------
// Tensor-core causal flash attention (tf32).
// grid = (SEQ/128, B*H), block = 256 (8 warps x 16 query rows).
// Key tile 64. K-fragments via ldmatrix.x4 (conflict-free, stride 68);
// V-fragments scalar LDS (wavefront-optimal). Softmax in registers;
// P C-frag -> A-frag via shuffles. Heavy query tiles first. Writes [B,T,C].
// ---------------------------------------------------------------------------
#define KV_LD 68

__global__ __launch_bounds__(256)
void attn_tc(float* __restrict__ out)
{
    const int qt   = gridDim.x - 1 - blockIdx.x;
    const int bh   = blockIdx.y;
    const int b    = bh >> 4;
    const int h    = bh & 15;
    const int tid  = threadIdx.x;
    const int warp = tid >> 5;
    const int lane = tid & 31;
    const int g    = lane >> 2;
    const int tg   = lane & 3;
    const int q0   = qt * 128;
    const int row_base = q0 + warp * 16;

    __shared__ float Ks[64][KV_LD];
    __shared__ float Vs[64][KV_LD];

    // ldmatrix lane address components for K frags (B-side, nb-pair per x4)
    const int klm_row = ((lane >> 4) << 3) + (lane & 7);
    const int klm_col = ((lane >> 3) & 1) * 4;

    // Q fragments (1/8 scale folded in; exact, power of two)
    const float* qp = g_q + ((size_t)bh * SEQ + row_base) * HDIM;
    uint32_t Qa[8][4];
    #pragma unroll
    for (int kb = 0; kb < 8; ++kb) {
        Qa[kb][0] = tf32u(0.125f * qp[(size_t)g        * 64 + kb * 8 + tg]);
        Qa[kb][1] = tf32u(0.125f * qp[(size_t)(g + 8)  * 64 + kb * 8 + tg]);
        Qa[kb][2] = tf32u(0.125f * qp[(size_t)g        * 64 + kb * 8 + tg + 4]);
        Qa[kb][3] = tf32u(0.125f * qp[(size_t)(g + 8)  * 64 + kb * 8 + tg + 4]);
    }

    float O[8][4];
    #pragma unroll
    for (int nb = 0; nb < 8; ++nb)
        #pragma unroll
        for (int e = 0; e < 4; ++e) O[nb][e] = 0.f;
    float m0 = -1e30f, m1 = -1e30f, l0 = 0.f, l1 = 0.f;

    const float* kt0 = g_k + (size_t)bh * SEQ * HDIM;
    const float* vt0 = g_v + (size_t)bh * SEQ * HDIM;

    const int njt = 2 * qt + 2;

    for (int jt = 0; jt < njt; ++jt) {
        const int j0 = jt * 64;
        __syncthreads();
        {
            const float4* kg = reinterpret_cast<const float4*>(kt0 + (size_t)j0 * HDIM);
            const float4* vg = reinterpret_cast<const float4*>(vt0 + (size_t)j0 * HDIM);
            #pragma unroll
            for (int u = 0; u < 4; ++u) {
                const int f = tid + u * 256;
                const int r = f >> 4;
                const int cI = f & 15;
                float4 k4 = kg[(size_t)r * 16 + cI];
                k4.x = f2tf32(k4.x); k4.y = f2tf32(k4.y);
                k4.z = f2tf32(k4.z); k4.w = f2tf32(k4.w);
                *reinterpret_cast<float4*>(&Ks[r][cI << 2]) = k4;
                float4 v4 = vg[(size_t)r * 16 + cI];
                v4.x = f2tf32(v4.x); v4.y = f2tf32(v4.y);
                v4.z = f2tf32(v4.z); v4.w = f2tf32(v4.w);
                *reinterpret_cast<float4*>(&Vs[r][cI << 2]) = v4;
            }
        }
        __syncthreads();

        // S = Q @ K^T; K B-frags via ldmatrix (2 nb per x4)
        float s[8][4];
        #pragma unroll
        for (int nb = 0; nb < 8; ++nb)
            #pragma unroll
            for (int e = 0; e < 4; ++e) s[nb][e] = 0.f;

        #pragma unroll
        for (int kb = 0; kb < 8; ++kb) {
            #pragma unroll
            for (int nbp = 0; nbp < 4; ++nbp) {
                const int nb0 = nbp * 2;
                uint32_t b00, b01, b10, b11;
                ldsm4(b00, b01, b10, b11,
                      &Ks[nb0 * 8 + klm_row][kb * 8 + klm_col]);
                MMA_TF32(s[nb0][0], s[nb0][1], s[nb0][2], s[nb0][3],
                         Qa[kb][0], Qa[kb][1], Qa[kb][2], Qa[kb][3], b00, b01);
                MMA_TF32(s[nb0+1][0], s[nb0+1][1], s[nb0+1][2], s[nb0+1][3],
                         Qa[kb][0], Qa[kb][1], Qa[kb][2], Qa[kb][3], b10, b11);
            }
        }

        // causal mask (only last two tiles can cross the diagonal)
        if (jt >= njt - 2) {
            #pragma unroll
            for (int nb = 0; nb < 8; ++nb) {
                #pragma unroll
                for (int e = 0; e < 4; ++e) {
                    const int col = j0 + nb * 8 + 2 * tg + (e & 1);
                    const int row = row_base + g + ((e >> 1) << 3);
                    if (col > row) s[nb][e] = -1e30f;
                }
            }
        }

        // online softmax
        float mt0 = m0, mt1 = m1;
        #pragma unroll
        for (int nb = 0; nb < 8; ++nb) {
            mt0 = fmaxf(mt0, fmaxf(s[nb][0], s[nb][1]));
            mt1 = fmaxf(mt1, fmaxf(s[nb][2], s[nb][3]));
        }
        mt0 = fmaxf(mt0, __shfl_xor_sync(0xffffffff, mt0, 1));
        mt0 = fmaxf(mt0, __shfl_xor_sync(0xffffffff, mt0, 2));
        mt1 = fmaxf(mt1, __shfl_xor_sync(0xffffffff, mt1, 1));
        mt1 = fmaxf(mt1, __shfl_xor_sync(0xffffffff, mt1, 2));

        const float al0 = __expf(m0 - mt0);
        const float al1 = __expf(m1 - mt1);
        l0 *= al0; l1 *= al1; m0 = mt0; m1 = mt1;
        #pragma unroll
        for (int nb = 0; nb < 8; ++nb) {
            O[nb][0] *= al0; O[nb][1] *= al0;
            O[nb][2] *= al1; O[nb][3] *= al1;
        }

        // P = exp(S - m); C-frag -> A-frag via shuffles; O += P @ V
        const int srcA = (lane & ~3) | (tg >> 1);
        const int srcB = srcA | 2;
        #pragma unroll
        for (int kb = 0; kb < 8; ++kb) {
            const float p0 = __expf(s[kb][0] - m0);
            const float p1 = __expf(s[kb][1] - m0);
            const float p2 = __expf(s[kb][2] - m1);
            const float p3 = __expf(s[kb][3] - m1);
            l0 += p0 + p1;
            l1 += p2 + p3;
            const float r0 = f2tf32(p0), r1 = f2tf32(p1);
            const float r2 = f2tf32(p2), r3 = f2tf32(p3);

            const float x0A = __shfl_sync(0xffffffff, r0, srcA);
            const float x1A = __shfl_sync(0xffffffff, r1, srcA);
            const float x0B = __shfl_sync(0xffffffff, r0, srcB);
            const float x1B = __shfl_sync(0xffffffff, r1, srcB);
            const float y0A = __shfl_sync(0xffffffff, r2, srcA);
            const float y1A = __shfl_sync(0xffffffff, r3, srcA);
            const float y0B = __shfl_sync(0xffffffff, r2, srcB);
            const float y1B = __shfl_sync(0xffffffff, r3, srcB);

            const uint32_t pa0 = __float_as_uint((tg & 1) ? x1A : x0A);
            const uint32_t pa1 = __float_as_uint((tg & 1) ? y1A : y0A);
            const uint32_t pa2 = __float_as_uint((tg & 1) ? x1B : x0B);
            const uint32_t pa3 = __float_as_uint((tg & 1) ? y1B : y0B);

            #pragma unroll
            for (int nb = 0; nb < 8; ++nb) {
                const uint32_t b0 = __float_as_uint(Vs[kb * 8 + tg    ][nb * 8 + g]);
                const uint32_t b1 = __float_as_uint(Vs[kb * 8 + tg + 4][nb * 8 + g]);
                MMA_TF32(O[nb][0], O[nb][1], O[nb][2], O[nb][3],
                         pa0, pa1, pa2, pa3, b0, b1);
            }
        }
    }

    // final l reduction across quad
    l0 += __shfl_xor_sync(0xffffffff, l0, 1);
    l0 += __shfl_xor_sync(0xffffffff, l0, 2);
    l1 += __shfl_xor_sync(0xffffffff, l1, 1);
    l1 += __shfl_xor_sync(0xffffffff, l1, 2);
    const float inv0 = 1.f / l0;
    const float inv1 = 1.f / l1;

    float* orow0 = out + ((size_t)b * SEQ + row_base + g    ) * CDIM + h * 64;
    float* orow1 = out + ((size_t)b * SEQ + row_base + g + 8) * CDIM + h * 64;
    #pragma unroll
    for (int nb = 0; nb < 8; ++nb) {
        const int cc = nb * 8 + 2 * tg;
        *reinterpret_cast<float2*>(orow0 + cc) =
            make_float2(O[nb][0] * inv0, O[nb][1] * inv0);
        *reinterpret_cast<float2*>(orow1 + cc) =
            make_float2(O[nb][2] * inv1, O[nb][3] * inv1);
    }
}

// ---------------------------------------------------------------------------
// Bridge head. Layout: y[4194304] | bridge_activated[2] | bridge_activations[204]
// ---------------------------------------------------------------------------
__global__ void bridge_kernel(const float* __restrict__ y,
                              const float* __restrict__ Wd,
                              const float* __restrict__ bd,
                              const int* __restrict__ idx32,
                              float* __restrict__ out)
{
    const int b = blockIdx.x;
    const int t = threadIdx.x;           // 128 threads
    __shared__ float red[128];
    __shared__ int is64;

    if (t == 0) {
        int z = 0;
        for (int i = 0; i < BSIZE / 2; ++i) z |= idx32[2 * i + 1];
        is64 = (z == 0) ? 1 : 0;
    }
    __syncthreads();

    float part = 0.f;
    if (t < BSIZE) {
        int c = is64 ? idx32[2 * t] : idx32[t];
        c &= (CDIM - 1);
        const float a = y[((size_t)b * SEQ + (SEQ - 1)) * CDIM + (size_t)c];
        out[(size_t)MROWS * CDIM + BATCH + b * BSIZE + t] = a;
        part = a * Wd[t];
    }
    red[t] = part;
    __syncthreads();
    for (int s = 64; s > 0; s >>= 1) {
        if (t < s) red[t] += red[t + s];
        __syncthreads();
    }
    if (t == 0) {
        const float sig = 1.f / (1.f + __expf(-(red[0] + bd[0])));
        out[(size_t)MROWS * CDIM + b] = (sig > 0.5f) ? 1.0f : 0.0f;
    }
}

// ---------------------------------------------------------------------------
extern "C" void kernel_launch(void* const* d_in, const int* in_sizes, int n_in,
                              void* d_out, int out_size)
{
    const float* x   = (const float*)d_in[0];
    const float* Wq  = (const float*)d_in[1];
    const float* bq  = (const float*)d_in[2];
    const float* Wk  = (const float*)d_in[3];
    const float* bk  = (const float*)d_in[4];
    const float* Wv  = (const float*)d_in[5];
    const float* bv  = (const float*)d_in[6];
    const float* Wp  = (const float*)d_in[7];
    const float* bp  = (const float*)d_in[8];
    const float* Wd  = (const float*)d_in[9];
    const float* bd  = (const float*)d_in[10];
    const int*   bidx = (const int*)d_in[11];
    float* out = (float*)d_out;

    float *gq, *gk, *gv, *gatt;
    cudaGetSymbolAddress((void**)&gq,  g_q);
    cudaGetSymbolAddress((void**)&gk,  g_k);
    cudaGetSymbolAddress((void**)&gv,  g_v);
    cudaGetSymbolAddress((void**)&gatt, g_att);

    static int smem_set = 0;
    if (!smem_set) {
        cudaFuncSetAttribute(gemm_tf32,
                             cudaFuncAttributeMaxDynamicSharedMemorySize, GSMEM);
        smem_set = 1;
    }

    dim3 ggrid(CDIM / BN, MROWS / BM);   // (8, 32)
    gemm_tf32<<<ggrid, 256, GSMEM>>>(x, Wq, bq, gq, 0);
    gemm_tf32<<<ggrid, 256, GSMEM>>>(x, Wk, bk, gk, 0);
    gemm_tf32<<<ggrid, 256, GSMEM>>>(x, Wv, bv, gv, 0);

    attn_tc<<<dim3(SEQ / 128, BATCH * NHEAD), 256>>>(gatt);

    gemm_tf32<<<ggrid, 256, GSMEM>>>(gatt, Wp, bp, out, 1);

    bridge_kernel<<<BATCH, 128>>>(out, Wd, bd, bidx, out);
}

// round 6
// speedup vs baseline: 4.7807x; 1.0477x over previous
#include <cuda_runtime.h>
#include <cuda_bf16.h>
#include <cstdint>

// Problem constants
#define BATCH 2
#define SEQ   2048
#define CDIM  1024
#define NHEAD 16
#define HDIM  64
#define MROWS (BATCH*SEQ)      // 4096
#define BSIZE 102

// Scratch (device globals: allocation-free)
__device__ float g_q[BATCH*NHEAD*SEQ*HDIM];   // [B,H,T,D] (tf32-rounded)
__device__ float g_k[BATCH*NHEAD*SEQ*HDIM];
__device__ float g_v[BATCH*NHEAD*SEQ*HDIM];
__device__ float g_att[MROWS*CDIM];           // [B,T,C]  (tf32-rounded)
__device__ float g_xr[MROWS*CDIM];            // tf32-rounded x
__device__ float g_wr[4*CDIM*CDIM];           // tf32-rounded Wq,Wk,Wv,Wp

// ---------------------------------------------------------------------------
// helpers
// ---------------------------------------------------------------------------
__device__ __forceinline__ float f2tf32(float f) {
    uint32_t r;
    asm("cvt.rna.tf32.f32 %0, %1;" : "=r"(r) : "f"(f));
    return __uint_as_float(r);
}

#define MMA_TF32(c0,c1,c2,c3,a0,a1,a2,a3,b0,b1)                          \
    asm volatile("mma.sync.aligned.m16n8k8.row.col.f32.tf32.tf32.f32 "  \
                 "{%0,%1,%2,%3},{%4,%5,%6,%7},{%8,%9},{%0,%1,%2,%3};"   \
                 : "+f"(c0), "+f"(c1), "+f"(c2), "+f"(c3)               \
                 : "r"(a0), "r"(a1), "r"(a2), "r"(a3), "r"(b0), "r"(b1))

__device__ __forceinline__ void ldsm4(uint32_t& r0, uint32_t& r1,
                                      uint32_t& r2, uint32_t& r3,
                                      const void* p) {
    uint32_t s = (uint32_t)__cvta_generic_to_shared(p);
    asm volatile("ldmatrix.sync.aligned.m8n8.x4.shared.b16 {%0,%1,%2,%3}, [%4];"
                 : "=r"(r0), "=r"(r1), "=r"(r2), "=r"(r3) : "r"(s));
}

__device__ __forceinline__ void cp16(void* smem_dst, const void* gptr) {
    uint32_t s = (uint32_t)__cvta_generic_to_shared(smem_dst);
    asm volatile("cp.async.cg.shared.global [%0], [%1], 16;" :: "r"(s), "l"(gptr));
}
#define CP_COMMIT() asm volatile("cp.async.commit_group;")
#define CP_WAIT(n)  asm volatile("cp.async.wait_group %0;" :: "n"(n))

// ---------------------------------------------------------------------------
// Pre-round fp32 -> tf32 (rna), float4 grid-stride
// ---------------------------------------------------------------------------
__global__ void round_tf32(const float4* __restrict__ src,
                           float4* __restrict__ dst, int n4)
{
    for (int i = blockIdx.x * blockDim.x + threadIdx.x; i < n4;
         i += gridDim.x * blockDim.x) {
        float4 v = src[i];
        v.x = f2tf32(v.x); v.y = f2tf32(v.y);
        v.z = f2tf32(v.z); v.w = f2tf32(v.w);
        dst[i] = v;
    }
}

// ---------------------------------------------------------------------------
// tf32 tensor-core GEMM, cp.async double-buffered, ldmatrix A-frags.
// Inputs pre-rounded to tf32 -> no cvt in hot loop.
// C[M,N] = A[M,K] @ W[K,N] + bias.  M=4096, N=K=1024.
// CTA 128x128, K-tile 32, 4 warps (64x64 warp tile), 128 threads.
// mode 0: scatter rounded output into [B,H,T,D]; mode 1: row-major fp32
// ---------------------------------------------------------------------------
#define BM 128
#define BN 128
#define BK 32
#define AS_LD 36
#define BS_LD 136
#define AS_SZ (BM*AS_LD)                    // 4608 floats
#define BS_SZ (BK*BS_LD)                    // 4352 floats
#define GSMEM ((2*AS_SZ + 2*BS_SZ)*4)       // 71680 bytes

__global__ __launch_bounds__(128)
void gemm_tf32(const float* __restrict__ A, const float* __restrict__ W,
               const float* __restrict__ bias, float* __restrict__ C, int mode)
{
    const int K = CDIM, N = CDIM;
    extern __shared__ float sm[];
    float* As = sm;
    float* Bs = sm + 2 * AS_SZ;

    const int tid  = threadIdx.x;
    const int rowBase = blockIdx.y * BM;
    const int colBase = blockIdx.x * BN;

    const int w    = tid >> 5;
    const int lane = tid & 31;
    const int g    = lane >> 2;
    const int tg   = lane & 3;
    const int wm   = (w >> 1) * 64;
    const int wn   = (w & 1) * 64;

    const int lm_row = ((lane >> 3) & 1) * 8 + (lane & 7);
    const int lm_col = (lane >> 4) * 4;

    float c[4][8][4] = {};
    const int ntiles = K / BK;

    auto issue = [&](int buf, int kt) {
        const int k0 = kt * BK;
        #pragma unroll
        for (int i = 0; i < 8; ++i) {
            const int f = tid + i * 128;
            const int ar = f >> 3, ac = f & 7;
            cp16(&As[buf * AS_SZ + ar * AS_LD + ac * 4],
                 &A[(size_t)(rowBase + ar) * K + k0 + ac * 4]);
            const int br = f >> 5, bc = f & 31;
            cp16(&Bs[buf * BS_SZ + br * BS_LD + bc * 4],
                 &W[(size_t)(k0 + br) * N + colBase + bc * 4]);
        }
        CP_COMMIT();
    };

    int buf = 0;
    issue(0, 0);

    for (int kt = 0; kt < ntiles; ++kt) {
        if (kt + 1 < ntiles) {
            issue(buf ^ 1, kt + 1);
            CP_WAIT(1);
        } else {
            CP_WAIT(0);
        }
        __syncthreads();

        const float* Ab = As + buf * AS_SZ;
        const float* Bb = Bs + buf * BS_SZ;

        #pragma unroll
        for (int ks = 0; ks < BK / 8; ++ks) {
            const int kb = ks * 8;
            uint32_t af[4][4];
            #pragma unroll
            for (int mi = 0; mi < 4; ++mi) {
                const int r = wm + mi * 16 + lm_row;
                ldsm4(af[mi][0], af[mi][1], af[mi][2], af[mi][3],
                      &Ab[r * AS_LD + kb + lm_col]);
            }
            uint32_t bf[8][2];
            #pragma unroll
            for (int ni = 0; ni < 8; ++ni) {
                const int n0 = wn + ni * 8 + g;
                bf[ni][0] = __float_as_uint(Bb[(kb + tg    ) * BS_LD + n0]);
                bf[ni][1] = __float_as_uint(Bb[(kb + tg + 4) * BS_LD + n0]);
            }
            #pragma unroll
            for (int mi = 0; mi < 4; ++mi)
                #pragma unroll
                for (int ni = 0; ni < 8; ++ni)
                    MMA_TF32(c[mi][ni][0], c[mi][ni][1], c[mi][ni][2], c[mi][ni][3],
                             af[mi][0], af[mi][1], af[mi][2], af[mi][3],
                             bf[ni][0], bf[ni][1]);
        }
        __syncthreads();
        buf ^= 1;
    }

    #pragma unroll
    for (int mi = 0; mi < 4; ++mi) {
        #pragma unroll
        for (int ni = 0; ni < 8; ++ni) {
            #pragma unroll
            for (int e = 0; e < 4; ++e) {
                const int r  = rowBase + wm + mi * 16 + g + ((e >> 1) << 3);
                const int cc = colBase + wn + ni * 8 + 2 * tg + (e & 1);
                const float val = c[mi][ni][e] + bias[cc];
                if (mode == 0) {
                    const int b = r >> 11;
                    const int t = r & (SEQ - 1);
                    const int h = cc >> 6;
                    const int d = cc & (HDIM - 1);
                    C[(((size_t)b * NHEAD + h) * SEQ + t) * HDIM + d] = f2tf32(val);
                } else {
                    C[(size_t)r * CDIM + cc] = val;
                }
            }
        }
    }
}

// ---------------------------------------------------------------------------
// Tensor-core causal flash attention (tf32).
// grid = (SEQ/128, B*H), block = 128 (4 warps x 32 query rows).
// Key tile 64. All inputs pre-rounded -> no cvt. K frags via ldmatrix.x4
// reused by both 16-row m-blocks; V scalar LDS likewise reused.
// Output written tf32-rounded (input to final GEMM). Heavy tiles first.
// ---------------------------------------------------------------------------
#define KV_LD 68

__global__ __launch_bounds__(128)
void attn_tc(float* __restrict__ out)
{
    const int qt   = gridDim.x - 1 - blockIdx.x;
    const int bh   = blockIdx.y;
    const int b    = bh >> 4;
    const int h    = bh & 15;
    const int tid  = threadIdx.x;
    const int warp = tid >> 5;
    const int lane = tid & 31;
    const int g    = lane >> 2;
    const int tg   = lane & 3;
    const int q0   = qt * 128;
    const int row_base = q0 + warp * 32;

    __shared__ float Ks[64][KV_LD];
    __shared__ float Vs[64][KV_LD];

    const int klm_row = ((lane >> 4) << 3) + (lane & 7);
    const int klm_col = ((lane >> 3) & 1) * 4;

    // Q fragments: pre-rounded; x0.125 is a power of 2 -> stays tf32-exact
    const float* qp = g_q + ((size_t)bh * SEQ + row_base) * HDIM;
    uint32_t Qa[2][8][4];
    #pragma unroll
    for (int mi = 0; mi < 2; ++mi) {
        #pragma unroll
        for (int kb = 0; kb < 8; ++kb) {
            Qa[mi][kb][0] = __float_as_uint(0.125f * qp[(size_t)(mi*16 + g    ) * 64 + kb*8 + tg]);
            Qa[mi][kb][1] = __float_as_uint(0.125f * qp[(size_t)(mi*16 + g + 8) * 64 + kb*8 + tg]);
            Qa[mi][kb][2] = __float_as_uint(0.125f * qp[(size_t)(mi*16 + g    ) * 64 + kb*8 + tg + 4]);
            Qa[mi][kb][3] = __float_as_uint(0.125f * qp[(size_t)(mi*16 + g + 8) * 64 + kb*8 + tg + 4]);
        }
    }

    float O[2][8][4];
    #pragma unroll
    for (int mi = 0; mi < 2; ++mi)
        #pragma unroll
        for (int nb = 0; nb < 8; ++nb)
            #pragma unroll
            for (int e = 0; e < 4; ++e) O[mi][nb][e] = 0.f;
    float mrow[2][2] = {{-1e30f, -1e30f}, {-1e30f, -1e30f}};
    float lrow[2][2] = {{0.f, 0.f}, {0.f, 0.f}};

    const float* kt0 = g_k + (size_t)bh * SEQ * HDIM;
    const float* vt0 = g_v + (size_t)bh * SEQ * HDIM;

    const int njt = 2 * qt + 2;

    for (int jt = 0; jt < njt; ++jt) {
        const int j0 = jt * 64;
        __syncthreads();
        {
            const float4* kg = reinterpret_cast<const float4*>(kt0 + (size_t)j0 * HDIM);
            const float4* vg = reinterpret_cast<const float4*>(vt0 + (size_t)j0 * HDIM);
            #pragma unroll
            for (int u = 0; u < 8; ++u) {
                const int f = tid + u * 128;
                const int r = f >> 4;
                const int cI = f & 15;
                *reinterpret_cast<float4*>(&Ks[r][cI << 2]) = kg[(size_t)r * 16 + cI];
                *reinterpret_cast<float4*>(&Vs[r][cI << 2]) = vg[(size_t)r * 16 + cI];
            }
        }
        __syncthreads();

        // S = Q @ K^T; K B-frags via ldmatrix shared across both m-blocks
        float s[2][8][4];
        #pragma unroll
        for (int mi = 0; mi < 2; ++mi)
            #pragma unroll
            for (int nb = 0; nb < 8; ++nb)
                #pragma unroll
                for (int e = 0; e < 4; ++e) s[mi][nb][e] = 0.f;

        #pragma unroll
        for (int kb = 0; kb < 8; ++kb) {
            #pragma unroll
            for (int nbp = 0; nbp < 4; ++nbp) {
                const int nb0 = nbp * 2;
                uint32_t b00, b01, b10, b11;
                ldsm4(b00, b01, b10, b11,
                      &Ks[nb0 * 8 + klm_row][kb * 8 + klm_col]);
                #pragma unroll
                for (int mi = 0; mi < 2; ++mi) {
                    MMA_TF32(s[mi][nb0][0], s[mi][nb0][1], s[mi][nb0][2], s[mi][nb0][3],
                             Qa[mi][kb][0], Qa[mi][kb][1], Qa[mi][kb][2], Qa[mi][kb][3],
                             b00, b01);
                    MMA_TF32(s[mi][nb0+1][0], s[mi][nb0+1][1], s[mi][nb0+1][2], s[mi][nb0+1][3],
                             Qa[mi][kb][0], Qa[mi][kb][1], Qa[mi][kb][2], Qa[mi][kb][3],
                             b10, b11);
                }
            }
        }

        // causal mask (only last two tiles can cross the diagonal)
        if (jt >= njt - 2) {
            #pragma unroll
            for (int mi = 0; mi < 2; ++mi)
                #pragma unroll
                for (int nb = 0; nb < 8; ++nb)
                    #pragma unroll
                    for (int e = 0; e < 4; ++e) {
                        const int col = j0 + nb * 8 + 2 * tg + (e & 1);
                        const int row = row_base + mi * 16 + g + ((e >> 1) << 3);
                        if (col > row) s[mi][nb][e] = -1e30f;
                    }
        }

        // online softmax per m-block
        #pragma unroll
        for (int mi = 0; mi < 2; ++mi) {
            float mt0 = mrow[mi][0], mt1 = mrow[mi][1];
            #pragma unroll
            for (int nb = 0; nb < 8; ++nb) {
                mt0 = fmaxf(mt0, fmaxf(s[mi][nb][0], s[mi][nb][1]));
                mt1 = fmaxf(mt1, fmaxf(s[mi][nb][2], s[mi][nb][3]));
            }
            mt0 = fmaxf(mt0, __shfl_xor_sync(0xffffffff, mt0, 1));
            mt0 = fmaxf(mt0, __shfl_xor_sync(0xffffffff, mt0, 2));
            mt1 = fmaxf(mt1, __shfl_xor_sync(0xffffffff, mt1, 1));
            mt1 = fmaxf(mt1, __shfl_xor_sync(0xffffffff, mt1, 2));

            const float al0 = __expf(mrow[mi][0] - mt0);
            const float al1 = __expf(mrow[mi][1] - mt1);
            lrow[mi][0] *= al0; lrow[mi][1] *= al1;
            mrow[mi][0] = mt0;  mrow[mi][1] = mt1;
            #pragma unroll
            for (int nb = 0; nb < 8; ++nb) {
                O[mi][nb][0] *= al0; O[mi][nb][1] *= al0;
                O[mi][nb][2] *= al1; O[mi][nb][3] *= al1;
            }
        }

        // P = exp(S-m); C-frag -> A-frag via shuffles; O += P @ V
        const int srcA = (lane & ~3) | (tg >> 1);
        const int srcB = srcA | 2;
        #pragma unroll
        for (int kb = 0; kb < 8; ++kb) {
            uint32_t pa[2][4];
            #pragma unroll
            for (int mi = 0; mi < 2; ++mi) {
                const float p0 = __expf(s[mi][kb][0] - mrow[mi][0]);
                const float p1 = __expf(s[mi][kb][1] - mrow[mi][0]);
                const float p2 = __expf(s[mi][kb][2] - mrow[mi][1]);
                const float p3 = __expf(s[mi][kb][3] - mrow[mi][1]);
                lrow[mi][0] += p0 + p1;
                lrow[mi][1] += p2 + p3;
                const float r0 = f2tf32(p0), r1 = f2tf32(p1);
                const float r2 = f2tf32(p2), r3 = f2tf32(p3);

                const float x0A = __shfl_sync(0xffffffff, r0, srcA);
                const float x1A = __shfl_sync(0xffffffff, r1, srcA);
                const float x0B = __shfl_sync(0xffffffff, r0, srcB);
                const float x1B = __shfl_sync(0xffffffff, r1, srcB);
                const float y0A = __shfl_sync(0xffffffff, r2, srcA);
                const float y1A = __shfl_sync(0xffffffff, r3, srcA);
                const float y0B = __shfl_sync(0xffffffff, r2, srcB);
                const float y1B = __shfl_sync(0xffffffff, r3, srcB);

                pa[mi][0] = __float_as_uint((tg & 1) ? x1A : x0A);
                pa[mi][1] = __float_as_uint((tg & 1) ? y1A : y0A);
                pa[mi][2] = __float_as_uint((tg & 1) ? x1B : x0B);
                pa[mi][3] = __float_as_uint((tg & 1) ? y1B : y0B);
            }

            #pragma unroll
            for (int nb = 0; nb < 8; ++nb) {
                const uint32_t b0 = __float_as_uint(Vs[kb * 8 + tg    ][nb * 8 + g]);
                const uint32_t b1 = __float_as_uint(Vs[kb * 8 + tg + 4][nb * 8 + g]);
                #pragma unroll
                for (int mi = 0; mi < 2; ++mi)
                    MMA_TF32(O[mi][nb][0], O[mi][nb][1], O[mi][nb][2], O[mi][nb][3],
                             pa[mi][0], pa[mi][1], pa[mi][2], pa[mi][3], b0, b1);
            }
        }
    }

    // epilogue: per m-block, reduce l, scale, round, store
    #pragma unroll
    for (int mi = 0; mi < 2; ++mi) {
        float l0 = lrow[mi][0], l1 = lrow[mi][1];
        l0 += __shfl_xor_sync(0xffffffff, l0, 1);
        l0 += __shfl_xor_sync(0xffffffff, l0, 2);
        l1 += __shfl_xor_sync(0xffffffff, l1, 1);
        l1 += __shfl_xor_sync(0xffffffff, l1, 2);
        const float inv0 = 1.f / l0;
        const float inv1 = 1.f / l1;

        float* orow0 = out + ((size_t)b * SEQ + row_base + mi*16 + g    ) * CDIM + h * 64;
        float* orow1 = out + ((size_t)b * SEQ + row_base + mi*16 + g + 8) * CDIM + h * 64;
        #pragma unroll
        for (int nb = 0; nb < 8; ++nb) {
            const int cc = nb * 8 + 2 * tg;
            *reinterpret_cast<float2*>(orow0 + cc) =
                make_float2(f2tf32(O[mi][nb][0] * inv0), f2tf32(O[mi][nb][1] * inv0));
            *reinterpret_cast<float2*>(orow1 + cc) =
                make_float2(f2tf32(O[mi][nb][2] * inv1), f2tf32(O[mi][nb][3] * inv1));
        }
    }
}

// ---------------------------------------------------------------------------
// Bridge head. Layout: y[4194304] | bridge_activated[2] | bridge_activations[204]
// ---------------------------------------------------------------------------
__global__ void bridge_kernel(const float* __restrict__ y,
                              const float* __restrict__ Wd,
                              const float* __restrict__ bd,
                              const int* __restrict__ idx32,
                              float* __restrict__ out)
{
    const int b = blockIdx.x;
    const int t = threadIdx.x;           // 128 threads
    __shared__ float red[128];
    __shared__ int is64;

    if (t == 0) {
        int z = 0;
        for (int i = 0; i < BSIZE / 2; ++i) z |= idx32[2 * i + 1];
        is64 = (z == 0) ? 1 : 0;
    }
    __syncthreads();

    float part = 0.f;
    if (t < BSIZE) {
        int c = is64 ? idx32[2 * t] : idx32[t];
        c &= (CDIM - 1);
        const float a = y[((size_t)b * SEQ + (SEQ - 1)) * CDIM + (size_t)c];
        out[(size_t)MROWS * CDIM + BATCH + b * BSIZE + t] = a;
        part = a * Wd[t];
    }
    red[t] = part;
    __syncthreads();
    for (int s = 64; s > 0; s >>= 1) {
        if (t < s) red[t] += red[t + s];
        __syncthreads();
    }
    if (t == 0) {
        const float sig = 1.f / (1.f + __expf(-(red[0] + bd[0])));
        out[(size_t)MROWS * CDIM + b] = (sig > 0.5f) ? 1.0f : 0.0f;
    }
}

// ---------------------------------------------------------------------------
extern "C" void kernel_launch(void* const* d_in, const int* in_sizes, int n_in,
                              void* d_out, int out_size)
{
    const float* x   = (const float*)d_in[0];
    const float* Wq  = (const float*)d_in[1];
    const float* bq  = (const float*)d_in[2];
    const float* Wk  = (const float*)d_in[3];
    const float* bk  = (const float*)d_in[4];
    const float* Wv  = (const float*)d_in[5];
    const float* bv  = (const float*)d_in[6];
    const float* Wp  = (const float*)d_in[7];
    const float* bp  = (const float*)d_in[8];
    const float* Wd  = (const float*)d_in[9];
    const float* bd  = (const float*)d_in[10];
    const int*   bidx = (const int*)d_in[11];
    float* out = (float*)d_out;

    float *gq, *gk, *gv, *gatt, *gxr, *gwr;
    cudaGetSymbolAddress((void**)&gq,  g_q);
    cudaGetSymbolAddress((void**)&gk,  g_k);
    cudaGetSymbolAddress((void**)&gv,  g_v);
    cudaGetSymbolAddress((void**)&gatt, g_att);
    cudaGetSymbolAddress((void**)&gxr, g_xr);
    cudaGetSymbolAddress((void**)&gwr, g_wr);

    static int smem_set = 0;
    if (!smem_set) {
        cudaFuncSetAttribute(gemm_tf32,
                             cudaFuncAttributeMaxDynamicSharedMemorySize, GSMEM);
        smem_set = 1;
    }

    const int WSZ = CDIM * CDIM;
    round_tf32<<<256, 256>>>((const float4*)x,  (float4*)gxr, MROWS * CDIM / 4);
    round_tf32<<<256, 256>>>((const float4*)Wq, (float4*)(gwr + 0 * WSZ), WSZ / 4);
    round_tf32<<<256, 256>>>((const float4*)Wk, (float4*)(gwr + 1 * WSZ), WSZ / 4);
    round_tf32<<<256, 256>>>((const float4*)Wv, (float4*)(gwr + 2 * WSZ), WSZ / 4);
    round_tf32<<<256, 256>>>((const float4*)Wp, (float4*)(gwr + 3 * WSZ), WSZ / 4);

    dim3 ggrid(CDIM / BN, MROWS / BM);   // (8, 32)
    gemm_tf32<<<ggrid, 128, GSMEM>>>(gxr, gwr + 0 * WSZ, bq, gq, 0);
    gemm_tf32<<<ggrid, 128, GSMEM>>>(gxr, gwr + 1 * WSZ, bk, gk, 0);
    gemm_tf32<<<ggrid, 128, GSMEM>>>(gxr, gwr + 2 * WSZ, bv, gv, 0);

    attn_tc<<<dim3(SEQ / 128, BATCH * NHEAD), 128>>>(gatt);

    gemm_tf32<<<ggrid, 128, GSMEM>>>(gatt, gwr + 3 * WSZ, bp, out, 1);

    bridge_kernel<<<BATCH, 128>>>(out, Wd, bd, bidx, out);
}

// round 8
// speedup vs baseline: 5.0988x; 1.0665x over previous
#include <cuda_runtime.h>
#include <cuda_bf16.h>
#include <cstdint>

// Problem constants
#define BATCH 2
#define SEQ   2048
#define CDIM  1024
#define NHEAD 16
#define HDIM  64
#define MROWS (BATCH*SEQ)      // 4096
#define BSIZE 102
#define QKV_SZ (BATCH*NHEAD*SEQ*HDIM)

// Scratch (device globals: allocation-free)
__device__ float g_qkv[3*QKV_SZ];             // q|k|v in [B,H,T,D] (tf32-rounded)
__device__ float g_att[MROWS*CDIM];           // [B,T,C]  (tf32-rounded)
__device__ float g_xr[MROWS*CDIM];            // tf32-rounded x
__device__ float g_wr[4*CDIM*CDIM];           // tf32-rounded Wq,Wk,Wv,Wp

// ---------------------------------------------------------------------------
// helpers
// ---------------------------------------------------------------------------
__device__ __forceinline__ float f2tf32(float f) {
    uint32_t r;
    asm("cvt.rna.tf32.f32 %0, %1;" : "=r"(r) : "f"(f));
    return __uint_as_float(r);
}

#define MMA_TF32(c0,c1,c2,c3,a0,a1,a2,a3,b0,b1)                          \
    asm volatile("mma.sync.aligned.m16n8k8.row.col.f32.tf32.tf32.f32 "  \
                 "{%0,%1,%2,%3},{%4,%5,%6,%7},{%8,%9},{%0,%1,%2,%3};"   \
                 : "+f"(c0), "+f"(c1), "+f"(c2), "+f"(c3)               \
                 : "r"(a0), "r"(a1), "r"(a2), "r"(a3), "r"(b0), "r"(b1))

__device__ __forceinline__ void ldsm4(uint32_t& r0, uint32_t& r1,
                                      uint32_t& r2, uint32_t& r3,
                                      const void* p) {
    uint32_t s = (uint32_t)__cvta_generic_to_shared(p);
    asm volatile("ldmatrix.sync.aligned.m8n8.x4.shared.b16 {%0,%1,%2,%3}, [%4];"
                 : "=r"(r0), "=r"(r1), "=r"(r2), "=r"(r3) : "r"(s));
}

__device__ __forceinline__ void cp16(void* smem_dst, const void* gptr) {
    uint32_t s = (uint32_t)__cvta_generic_to_shared(smem_dst);
    asm volatile("cp.async.cg.shared.global [%0], [%1], 16;" :: "r"(s), "l"(gptr));
}
#define CP_COMMIT() asm volatile("cp.async.commit_group;")
#define CP_WAIT(n)  asm volatile("cp.async.wait_group %0;" :: "n"(n))

// ---------------------------------------------------------------------------
// Fused prep: round x and the four W's to tf32 in one launch.
// grid = (G, 5); seg 0 = x, segs 1..4 = Wq,Wk,Wv,Wp.
// ---------------------------------------------------------------------------
__global__ void prep_round(const float4* __restrict__ x,
                           const float4* __restrict__ wq,
                           const float4* __restrict__ wk,
                           const float4* __restrict__ wv,
                           const float4* __restrict__ wp,
                           float4* __restrict__ xr,
                           float4* __restrict__ wr)
{
    const int seg = blockIdx.y;
    const float4* src;
    float4* dst;
    int n4;
    if (seg == 0) { src = x;  dst = xr; n4 = MROWS * CDIM / 4; }
    else {
        src = (seg == 1) ? wq : (seg == 2) ? wk : (seg == 3) ? wv : wp;
        dst = wr + (size_t)(seg - 1) * (CDIM * CDIM / 4);
        n4  = CDIM * CDIM / 4;
    }
    for (int i = blockIdx.x * blockDim.x + threadIdx.x; i < n4;
         i += gridDim.x * blockDim.x) {
        float4 v = src[i];
        v.x = f2tf32(v.x); v.y = f2tf32(v.y);
        v.z = f2tf32(v.z); v.w = f2tf32(v.w);
        dst[i] = v;
    }
}

// ---------------------------------------------------------------------------
// tf32 tensor-core GEMM body, cp.async double-buffered, ldmatrix A-frags.
// C[M,N] = A[M,K] @ W[K,N] + bias.  M=4096, N=K=1024.
// CTA 128x128, K-tile 32, 4 warps (64x64 warp tile), 128 threads.
// mode 0: scatter rounded output into [B,H,T,D]; mode 1: row-major fp32
// ---------------------------------------------------------------------------
#define BM 128
#define BN 128
#define BK 32
#define AS_LD 36
#define BS_LD 136
#define AS_SZ (BM*AS_LD)                    // 4608 floats
#define BS_SZ (BK*BS_LD)                    // 4352 floats
#define GSMEM ((2*AS_SZ + 2*BS_SZ)*4)       // 71680 bytes

__device__ __forceinline__
void gemm_body(const float* __restrict__ A, const float* __restrict__ W,
               const float* __restrict__ bias, float* __restrict__ C, int mode)
{
    const int K = CDIM, N = CDIM;
    extern __shared__ float sm[];
    float* As = sm;
    float* Bs = sm + 2 * AS_SZ;

    const int tid  = threadIdx.x;
    const int rowBase = blockIdx.y * BM;
    const int colBase = blockIdx.x * BN;

    const int w    = tid >> 5;
    const int lane = tid & 31;
    const int g    = lane >> 2;
    const int tg   = lane & 3;
    const int wm   = (w >> 1) * 64;
    const int wn   = (w & 1) * 64;

    const int lm_row = ((lane >> 3) & 1) * 8 + (lane & 7);
    const int lm_col = (lane >> 4) * 4;

    float c[4][8][4] = {};
    const int ntiles = K / BK;

    auto issue = [&](int buf, int kt) {
        const int k0 = kt * BK;
        #pragma unroll
        for (int i = 0; i < 8; ++i) {
            const int f = tid + i * 128;
            const int ar = f >> 3, ac = f & 7;
            cp16(&As[buf * AS_SZ + ar * AS_LD + ac * 4],
                 &A[(size_t)(rowBase + ar) * K + k0 + ac * 4]);
            const int br = f >> 5, bc = f & 31;
            cp16(&Bs[buf * BS_SZ + br * BS_LD + bc * 4],
                 &W[(size_t)(k0 + br) * N + colBase + bc * 4]);
        }
        CP_COMMIT();
    };

    int buf = 0;
    issue(0, 0);

    for (int kt = 0; kt < ntiles; ++kt) {
        if (kt + 1 < ntiles) {
            issue(buf ^ 1, kt + 1);
            CP_WAIT(1);
        } else {
            CP_WAIT(0);
        }
        __syncthreads();

        const float* Ab = As + buf * AS_SZ;
        const float* Bb = Bs + buf * BS_SZ;

        #pragma unroll
        for (int ks = 0; ks < BK / 8; ++ks) {
            const int kb = ks * 8;
            uint32_t af[4][4];
            #pragma unroll
            for (int mi = 0; mi < 4; ++mi) {
                const int r = wm + mi * 16 + lm_row;
                ldsm4(af[mi][0], af[mi][1], af[mi][2], af[mi][3],
                      &Ab[r * AS_LD + kb + lm_col]);
            }
            uint32_t bf[8][2];
            #pragma unroll
            for (int ni = 0; ni < 8; ++ni) {
                const int n0 = wn + ni * 8 + g;
                bf[ni][0] = __float_as_uint(Bb[(kb + tg    ) * BS_LD + n0]);
                bf[ni][1] = __float_as_uint(Bb[(kb + tg + 4) * BS_LD + n0]);
            }
            #pragma unroll
            for (int mi = 0; mi < 4; ++mi)
                #pragma unroll
                for (int ni = 0; ni < 8; ++ni)
                    MMA_TF32(c[mi][ni][0], c[mi][ni][1], c[mi][ni][2], c[mi][ni][3],
                             af[mi][0], af[mi][1], af[mi][2], af[mi][3],
                             bf[ni][0], bf[ni][1]);
        }
        __syncthreads();
        buf ^= 1;
    }

    #pragma unroll
    for (int mi = 0; mi < 4; ++mi) {
        #pragma unroll
        for (int ni = 0; ni < 8; ++ni) {
            #pragma unroll
            for (int e = 0; e < 4; ++e) {
                const int r  = rowBase + wm + mi * 16 + g + ((e >> 1) << 3);
                const int cc = colBase + wn + ni * 8 + 2 * tg + (e & 1);
                const float val = c[mi][ni][e] + bias[cc];
                if (mode == 0) {
                    const int b = r >> 11;
                    const int t = r & (SEQ - 1);
                    const int h = cc >> 6;
                    const int d = cc & (HDIM - 1);
                    C[(((size_t)b * NHEAD + h) * SEQ + t) * HDIM + d] = f2tf32(val);
                } else {
                    C[(size_t)r * CDIM + cc] = val;
                }
            }
        }
    }
}

// Fused QKV GEMM: grid.z in {0,1,2} selects weight/bias/output slice.
__global__ __launch_bounds__(128)
void gemm_qkv(const float* __restrict__ A, const float* __restrict__ Wbase,
              const float* __restrict__ b0, const float* __restrict__ b1,
              const float* __restrict__ b2, float* __restrict__ outBase)
{
    const int z = blockIdx.z;
    const float* bias = (z == 0) ? b0 : (z == 1) ? b1 : b2;
    gemm_body(A, Wbase + (size_t)z * CDIM * CDIM, bias,
              outBase + (size_t)z * QKV_SZ, 0);
}

__global__ __launch_bounds__(128)
void gemm_proj(const float* __restrict__ A, const float* __restrict__ W,
               const float* __restrict__ bias, float* __restrict__ C)
{
    gemm_body(A, W, bias, C, 1);
}

// ---------------------------------------------------------------------------
// Tensor-core causal flash attention (tf32), cp.async double-buffered K/V.
// grid = (SEQ/128, B*H), block = 128 (4 warps x 32 query rows).
// Key tile 64. K frags via ldmatrix.x4 shared across m-blocks; V scalar LDS.
// Output tf32-rounded. Heavy query tiles first. Writes [B,T,C].
// ---------------------------------------------------------------------------
#define KV_LD 68
#define KV_BUF (64*KV_LD)                    // floats per tile buffer
#define ASMEM (4*KV_BUF*4)                   // 69632 bytes (2xK + 2xV)

__global__ __launch_bounds__(128)
void attn_tc(float* __restrict__ out)
{
    const int qt   = gridDim.x - 1 - blockIdx.x;
    const int bh   = blockIdx.y;
    const int b    = bh >> 4;
    const int h    = bh & 15;
    const int tid  = threadIdx.x;
    const int warp = tid >> 5;
    const int lane = tid & 31;
    const int g    = lane >> 2;
    const int tg   = lane & 3;
    const int q0   = qt * 128;
    const int row_base = q0 + warp * 32;

    extern __shared__ float smA[];
    // layout: K buf0 | K buf1 | V buf0 | V buf1
    float* KsB = smA;
    float* VsB = smA + 2 * KV_BUF;

    const int klm_row = ((lane >> 4) << 3) + (lane & 7);
    const int klm_col = ((lane >> 3) & 1) * 4;

    const float* kt0 = g_qkv + 1 * QKV_SZ + (size_t)bh * SEQ * HDIM;
    const float* vt0 = g_qkv + 2 * QKV_SZ + (size_t)bh * SEQ * HDIM;

    // Q fragments: pre-rounded; x0.125 is a power of 2 -> stays tf32-exact
    const float* qp = g_qkv + ((size_t)bh * SEQ + row_base) * HDIM;
    uint32_t Qa[2][8][4];
    #pragma unroll
    for (int mi = 0; mi < 2; ++mi) {
        #pragma unroll
        for (int kb = 0; kb < 8; ++kb) {
            Qa[mi][kb][0] = __float_as_uint(0.125f * qp[(size_t)(mi*16 + g    ) * 64 + kb*8 + tg]);
            Qa[mi][kb][1] = __float_as_uint(0.125f * qp[(size_t)(mi*16 + g + 8) * 64 + kb*8 + tg]);
            Qa[mi][kb][2] = __float_as_uint(0.125f * qp[(size_t)(mi*16 + g    ) * 64 + kb*8 + tg + 4]);
            Qa[mi][kb][3] = __float_as_uint(0.125f * qp[(size_t)(mi*16 + g + 8) * 64 + kb*8 + tg + 4]);
        }
    }

    float O[2][8][4];
    #pragma unroll
    for (int mi = 0; mi < 2; ++mi)
        #pragma unroll
        for (int nb = 0; nb < 8; ++nb)
            #pragma unroll
            for (int e = 0; e < 4; ++e) O[mi][nb][e] = 0.f;
    float mrow[2][2] = {{-1e30f, -1e30f}, {-1e30f, -1e30f}};
    float lrow[2][2] = {{0.f, 0.f}, {0.f, 0.f}};

    const int njt = 2 * qt + 2;

    // cp.async staging of one 64x64 K tile + V tile into buffer bi
    auto issue = [&](int bi, int jt) {
        const int j0 = jt * 64;
        const float* kp = kt0 + (size_t)j0 * HDIM;
        const float* vp = vt0 + (size_t)j0 * HDIM;
        float* Kd = KsB + bi * KV_BUF;
        float* Vd = VsB + bi * KV_BUF;
        #pragma unroll
        for (int u = 0; u < 8; ++u) {
            const int f = tid + u * 128;     // 0..1023 float4 chunks
            const int r = f >> 4;
            const int cI = (f & 15) << 2;
            cp16(&Kd[r * KV_LD + cI], kp + (size_t)r * HDIM + cI);
            cp16(&Vd[r * KV_LD + cI], vp + (size_t)r * HDIM + cI);
        }
        CP_COMMIT();
    };

    int buf = 0;
    issue(0, 0);

    for (int jt = 0; jt < njt; ++jt) {
        const int j0 = jt * 64;
        if (jt + 1 < njt) {
            issue(buf ^ 1, jt + 1);
            CP_WAIT(1);
        } else {
            CP_WAIT(0);
        }
        __syncthreads();

        const float* Kb = KsB + buf * KV_BUF;
        const float* Vb = VsB + buf * KV_BUF;

        // S = Q @ K^T; K B-frags via ldmatrix shared across both m-blocks
        float s[2][8][4];
        #pragma unroll
        for (int mi = 0; mi < 2; ++mi)
            #pragma unroll
            for (int nb = 0; nb < 8; ++nb)
                #pragma unroll
                for (int e = 0; e < 4; ++e) s[mi][nb][e] = 0.f;

        #pragma unroll
        for (int kb = 0; kb < 8; ++kb) {
            #pragma unroll
            for (int nbp = 0; nbp < 4; ++nbp) {
                const int nb0 = nbp * 2;
                uint32_t b00, b01, b10, b11;
                ldsm4(b00, b01, b10, b11,
                      &Kb[(nb0 * 8 + klm_row) * KV_LD + kb * 8 + klm_col]);
                #pragma unroll
                for (int mi = 0; mi < 2; ++mi) {
                    MMA_TF32(s[mi][nb0][0], s[mi][nb0][1], s[mi][nb0][2], s[mi][nb0][3],
                             Qa[mi][kb][0], Qa[mi][kb][1], Qa[mi][kb][2], Qa[mi][kb][3],
                             b00, b01);
                    MMA_TF32(s[mi][nb0+1][0], s[mi][nb0+1][1], s[mi][nb0+1][2], s[mi][nb0+1][3],
                             Qa[mi][kb][0], Qa[mi][kb][1], Qa[mi][kb][2], Qa[mi][kb][3],
                             b10, b11);
                }
            }
        }

        // causal mask (only last two tiles can cross the diagonal)
        if (jt >= njt - 2) {
            #pragma unroll
            for (int mi = 0; mi < 2; ++mi)
                #pragma unroll
                for (int nb = 0; nb < 8; ++nb)
                    #pragma unroll
                    for (int e = 0; e < 4; ++e) {
                        const int col = j0 + nb * 8 + 2 * tg + (e & 1);
                        const int row = row_base + mi * 16 + g + ((e >> 1) << 3);
                        if (col > row) s[mi][nb][e] = -1e30f;
                    }
        }

        // online softmax per m-block
        #pragma unroll
        for (int mi = 0; mi < 2; ++mi) {
            float mt0 = mrow[mi][0], mt1 = mrow[mi][1];
            #pragma unroll
            for (int nb = 0; nb < 8; ++nb) {
                mt0 = fmaxf(mt0, fmaxf(s[mi][nb][0], s[mi][nb][1]));
                mt1 = fmaxf(mt1, fmaxf(s[mi][nb][2], s[mi][nb][3]));
            }
            mt0 = fmaxf(mt0, __shfl_xor_sync(0xffffffff, mt0, 1));
            mt0 = fmaxf(mt0, __shfl_xor_sync(0xffffffff, mt0, 2));
            mt1 = fmaxf(mt1, __shfl_xor_sync(0xffffffff, mt1, 1));
            mt1 = fmaxf(mt1, __shfl_xor_sync(0xffffffff, mt1, 2));

            const float al0 = __expf(mrow[mi][0] - mt0);
            const float al1 = __expf(mrow[mi][1] - mt1);
            lrow[mi][0] *= al0; lrow[mi][1] *= al1;
            mrow[mi][0] = mt0;  mrow[mi][1] = mt1;
            #pragma unroll
            for (int nb = 0; nb < 8; ++nb) {
                O[mi][nb][0] *= al0; O[mi][nb][1] *= al0;
                O[mi][nb][2] *= al1; O[mi][nb][3] *= al1;
            }
        }

        // P = exp(S-m); C-frag -> A-frag via shuffles; O += P @ V
        const int srcA = (lane & ~3) | (tg >> 1);
        const int srcB = srcA | 2;
        #pragma unroll
        for (int kb = 0; kb < 8; ++kb) {
            uint32_t pa[2][4];
            #pragma unroll
            for (int mi = 0; mi < 2; ++mi) {
                const float p0 = __expf(s[mi][kb][0] - mrow[mi][0]);
                const float p1 = __expf(s[mi][kb][1] - mrow[mi][0]);
                const float p2 = __expf(s[mi][kb][2] - mrow[mi][1]);
                const float p3 = __expf(s[mi][kb][3] - mrow[mi][1]);
                lrow[mi][0] += p0 + p1;
                lrow[mi][1] += p2 + p3;
                const float r0 = f2tf32(p0), r1 = f2tf32(p1);
                const float r2 = f2tf32(p2), r3 = f2tf32(p3);

                const float x0A = __shfl_sync(0xffffffff, r0, srcA);
                const float x1A = __shfl_sync(0xffffffff, r1, srcA);
                const float x0B = __shfl_sync(0xffffffff, r0, srcB);
                const float x1B = __shfl_sync(0xffffffff, r1, srcB);
                const float y0A = __shfl_sync(0xffffffff, r2, srcA);
                const float y1A = __shfl_sync(0xffffffff, r3, srcA);
                const float y0B = __shfl_sync(0xffffffff, r2, srcB);
                const float y1B = __shfl_sync(0xffffffff, r3, srcB);

                pa[mi][0] = __float_as_uint((tg & 1) ? x1A : x0A);
                pa[mi][1] = __float_as_uint((tg & 1) ? y1A : y0A);
                pa[mi][2] = __float_as_uint((tg & 1) ? x1B : x0B);
                pa[mi][3] = __float_as_uint((tg & 1) ? y1B : y0B);
            }

            #pragma unroll
            for (int nb = 0; nb < 8; ++nb) {
                const uint32_t b0 = __float_as_uint(Vb[(kb * 8 + tg    ) * KV_LD + nb * 8 + g]);
                const uint32_t b1 = __float_as_uint(Vb[(kb * 8 + tg + 4) * KV_LD + nb * 8 + g]);
                #pragma unroll
                for (int mi = 0; mi < 2; ++mi)
                    MMA_TF32(O[mi][nb][0], O[mi][nb][1], O[mi][nb][2], O[mi][nb][3],
                             pa[mi][0], pa[mi][1], pa[mi][2], pa[mi][3], b0, b1);
            }
        }
        __syncthreads();
        buf ^= 1;
    }

    // epilogue: per m-block, reduce l, scale, round, store
    #pragma unroll
    for (int mi = 0; mi < 2; ++mi) {
        float l0 = lrow[mi][0], l1 = lrow[mi][1];
        l0 += __shfl_xor_sync(0xffffffff, l0, 1);
        l0 += __shfl_xor_sync(0xffffffff, l0, 2);
        l1 += __shfl_xor_sync(0xffffffff, l1, 1);
        l1 += __shfl_xor_sync(0xffffffff, l1, 2);
        const float inv0 = 1.f / l0;
        const float inv1 = 1.f / l1;

        float* orow0 = out + ((size_t)b * SEQ + row_base + mi*16 + g    ) * CDIM + h * 64;
        float* orow1 = out + ((size_t)b * SEQ + row_base + mi*16 + g + 8) * CDIM + h * 64;
        #pragma unroll
        for (int nb = 0; nb < 8; ++nb) {
            const int cc = nb * 8 + 2 * tg;
            *reinterpret_cast<float2*>(orow0 + cc) =
                make_float2(f2tf32(O[mi][nb][0] * inv0), f2tf32(O[mi][nb][1] * inv0));
            *reinterpret_cast<float2*>(orow1 + cc) =
                make_float2(f2tf32(O[mi][nb][2] * inv1), f2tf32(O[mi][nb][3] * inv1));
        }
    }
}

// ---------------------------------------------------------------------------
// Bridge head. Layout: y[4194304] | bridge_activated[2] | bridge_activations[204]
// ---------------------------------------------------------------------------
__global__ void bridge_kernel(const float* __restrict__ y,
                              const float* __restrict__ Wd,
                              const float* __restrict__ bd,
                              const int* __restrict__ idx32,
                              float* __restrict__ out)
{
    const int b = blockIdx.x;
    const int t = threadIdx.x;           // 128 threads
    __shared__ float red[128];
    __shared__ int is64;

    if (t == 0) {
        int z = 0;
        for (int i = 0; i < BSIZE / 2; ++i) z |= idx32[2 * i + 1];
        is64 = (z == 0) ? 1 : 0;
    }
    __syncthreads();

    float part = 0.f;
    if (t < BSIZE) {
        int c = is64 ? idx32[2 * t] : idx32[t];
        c &= (CDIM - 1);
        const float a = y[((size_t)b * SEQ + (SEQ - 1)) * CDIM + (size_t)c];
        out[(size_t)MROWS * CDIM + BATCH + b * BSIZE + t] = a;
        part = a * Wd[t];
    }
    red[t] = part;
    __syncthreads();
    for (int s = 64; s > 0; s >>= 1) {
        if (t < s) red[t] += red[t + s];
        __syncthreads();
    }
    if (t == 0) {
        const float sig = 1.f / (1.f + __expf(-(red[0] + bd[0])));
        out[(size_t)MROWS * CDIM + b] = (sig > 0.5f) ? 1.0f : 0.0f;
    }
}

// ---------------------------------------------------------------------------
extern "C" void kernel_launch(void* const* d_in, const int* in_sizes, int n_in,
                              void* d_out, int out_size)
{
    const float* x   = (const float*)d_in[0];
    const float* Wq  = (const float*)d_in[1];
    const float* bq  = (const float*)d_in[2];
    const float* Wk  = (const float*)d_in[3];
    const float* bk  = (const float*)d_in[4];
    const float* Wv  = (const float*)d_in[5];
    const float* bv  = (const float*)d_in[6];
    const float* Wp  = (const float*)d_in[7];
    const float* bp  = (const float*)d_in[8];
    const float* Wd  = (const float*)d_in[9];
    const float* bd  = (const float*)d_in[10];
    const int*   bidx = (const int*)d_in[11];
    float* out = (float*)d_out;

    float *gqkv, *gatt, *gxr, *gwr;
    cudaGetSymbolAddress((void**)&gqkv, g_qkv);
    cudaGetSymbolAddress((void**)&gatt, g_att);
    cudaGetSymbolAddress((void**)&gxr, g_xr);
    cudaGetSymbolAddress((void**)&gwr, g_wr);

    static int attr_set = 0;
    if (!attr_set) {
        cudaFuncSetAttribute(gemm_qkv,
                             cudaFuncAttributeMaxDynamicSharedMemorySize, GSMEM);
        cudaFuncSetAttribute(gemm_proj,
                             cudaFuncAttributeMaxDynamicSharedMemorySize, GSMEM);
        cudaFuncSetAttribute(attn_tc,
                             cudaFuncAttributeMaxDynamicSharedMemorySize, ASMEM);
        attr_set = 1;
    }

    // 1) fused tf32 pre-rounding (x + 4 weights)
    prep_round<<<dim3(160, 5), 256>>>(
        (const float4*)x, (const float4*)Wq, (const float4*)Wk,
        (const float4*)Wv, (const float4*)Wp, (float4*)gxr, (float4*)gwr);

    // 2) fused QKV projection
    const int WSZ = CDIM * CDIM;
    gemm_qkv<<<dim3(CDIM / BN, MROWS / BM, 3), 128, GSMEM>>>(
        gxr, gwr, bq, bk, bv, gqkv);

    // 3) attention
    attn_tc<<<dim3(SEQ / 128, BATCH * NHEAD), 128, ASMEM>>>(gatt);

    // 4) output projection
    gemm_proj<<<dim3(CDIM / BN, MROWS / BM), 128, GSMEM>>>(
        gatt, gwr + 3 * WSZ, bp, out);

    // 5) bridge head
    bridge_kernel<<<BATCH, 128>>>(out, Wd, bd, bidx, out);
}